// round 16
// baseline (speedup 1.0000x reference)
#include <cuda_runtime.h>
#include <cuda_bf16.h>
#include <cstdint>
#include <math.h>

namespace {

typedef unsigned long long ull;
typedef __nv_bfloat16 bf16;

constexpr int  B_  = 128;
constexpr int  T_  = 256;
constexpr int  R_  = 130;
constexpr int  H_  = 1024;
constexpr int  H3_ = 3072;
constexpr int  Z2_ = 256;
constexpr int  C_  = 24;
constexpr int  ZC_ = 280;
constexpr long BT_ = (long)B_ * T_;
constexpr long BH_ = (long)B_ * H_;
constexpr long WN_ = (long)H3_ * H_;
constexpr int  KPAD = 192;

// ---- recurrence pipeline geometry (bulk-copy path) ----
constexpr int ACH   = 16384;              // A chunk bytes per half (128 x 128B)
constexpr int WCHE  = 6144;               // encoder W chunk (48 rows x 128B)
constexpr int WCHD  = 3072;               // decoder W chunk (24 rows x 128B)
constexpr int STG_E = 2 * ACH + 2 * WCHE;
constexpr int STG_D = 2 * ACH + 2 * WCHD;
constexpr int SMEM_E  = 3 * STG_E + 64;   // encoder: 3 stages, 1 CTA/SM
constexpr int SMEM_D2 = 2 * STG_D + 64;   // decoder: 2 stages, 2 CTAs/SM
constexpr long WTILE_E = 16L * WCHE;
constexpr long WTILE_D = 16L * WCHD;

// ---- batched-gemm smem geometry (cp.async path) ----
constexpr int KCH     = 64;
constexpr int ROWB    = 144;
constexpr int ABYTES  = 128 * ROWB;
constexpr int BBYT_G  = 64  * ROWB;
constexpr int STAGE_G = 2 * ABYTES + 2 * BBYT_G;
constexpr int SMEM_G  = 2 * STAGE_G;

// ------------------------- device scratch ----------------------------------
__device__ float g_hf[2][B_ * H_];
__device__ float g_hb[2][B_ * H_];
__device__ float g_h0[2][B_ * H_];
__device__ float g_h1[2][B_ * H_];
__device__ bf16 g_hfc_hi[2][B_ * H_], g_hfc_lo[2][B_ * H_];
__device__ bf16 g_hbc_hi[2][B_ * H_], g_hbc_lo[2][B_ * H_];
__device__ bf16 g_h0c_hi[2][B_ * H_], g_h0c_lo[2][B_ * H_];
__device__ bf16 g_h1c_hi[2][B_ * H_], g_h1c_lo[2][B_ * H_];
__device__ bf16 g_whhf_hi[WN_], g_whhf_lo[WN_];   // [64 jt][16 c][48 x 128B]
__device__ bf16 g_whhb_hi[WN_], g_whhb_lo[WN_];
__device__ bf16 g_whhg_hi[WN_], g_whhg_lo[WN_];   // [128 jt][16 c][24 x 128B]
__device__ bf16 g_wihg2_hi[WN_], g_wihg2_lo[WN_];
__device__ bf16 g_whhg2_hi[WN_], g_whhg2_lo[WN_];
__device__ bf16 g_xc_hi[BT_ * KPAD],  g_xc_lo[BT_ * KPAD];
__device__ bf16 g_dc_hi[BT_ * KPAD],  g_dc_lo[BT_ * KPAD];
__device__ bf16 g_wihf_hi[H3_ * KPAD], g_wihf_lo[H3_ * KPAD];
__device__ bf16 g_wihb_hi[H3_ * KPAD], g_wihb_lo[H3_ * KPAD];
__device__ bf16 g_wihg_hi[H3_ * KPAD], g_wihg_lo[H3_ * KPAD];
__device__ bf16 g_wout_hi[192 * H_],  g_wout_lo[192 * H_];
__device__ bf16 g_h1a_hi[BT_ * H_],   g_h1a_lo[BT_ * H_];
__device__ float g_gif[BT_ * H3_];
__device__ float g_gib[BT_ * H3_];
__device__ float g_gid[BT_ * H3_];
__device__ float g_zi [B_ * H3_];
__device__ float g_henc[B_ * 2 * H_];
__device__ float g_var [B_ * Z2_];
__device__ float g_zbuf[B_ * ZC_];
__device__ float g_decin[BT_ * R_];
__device__ float g_logits[BT_ * R_];
__device__ unsigned g_bar_count;
__device__ volatile unsigned g_bar_gen;

// --------------------------- helpers ----------------------------------------
__device__ __forceinline__ ull pack2(float x, float y) {
    ull r; asm("mov.b64 %0, {%1, %2};" : "=l"(r) : "f"(x), "f"(y)); return r;
}
__device__ __forceinline__ float2 unpack2(ull v) {
    float2 f; asm("mov.b64 {%0, %1}, %2;" : "=f"(f.x), "=f"(f.y) : "l"(v)); return f;
}
__device__ __forceinline__ void fma2(ull& d, ull a, ull b) {
    asm("fma.rn.f32x2 %0, %1, %2, %0;" : "+l"(d) : "l"(a), "l"(b));
}
__device__ __forceinline__ float sigmoidf_(float x) { return 1.f / (1.f + expf(-x)); }

__device__ __forceinline__ void ldsm4(uint32_t r[4], uint32_t addr) {
    asm volatile("ldmatrix.sync.aligned.m8n8.x4.shared.b16 {%0,%1,%2,%3}, [%4];"
                 : "=r"(r[0]), "=r"(r[1]), "=r"(r[2]), "=r"(r[3]) : "r"(addr));
}
__device__ __forceinline__ void ldsm2(uint32_t r[2], uint32_t addr) {
    asm volatile("ldmatrix.sync.aligned.m8n8.x2.shared.b16 {%0,%1}, [%2];"
                 : "=r"(r[0]), "=r"(r[1]) : "r"(addr));
}
__device__ __forceinline__ void mma16816(float d[4], const uint32_t a[4], const uint32_t b[2]) {
    asm volatile(
        "mma.sync.aligned.m16n8k16.row.col.f32.bf16.bf16.f32 "
        "{%0,%1,%2,%3}, {%4,%5,%6,%7}, {%8,%9}, {%0,%1,%2,%3};"
        : "+f"(d[0]), "+f"(d[1]), "+f"(d[2]), "+f"(d[3])
        : "r"(a[0]), "r"(a[1]), "r"(a[2]), "r"(a[3]), "r"(b[0]), "r"(b[1]));
}
__device__ __forceinline__ void cpa16(uint32_t dst, const void* src) {
    asm volatile("cp.async.cg.shared.global [%0], [%1], 16;" :: "r"(dst), "l"(src));
}
__device__ __forceinline__ void cp_commit() { asm volatile("cp.async.commit_group;"); }
template <int N> __device__ __forceinline__ void cp_wait() {
    asm volatile("cp.async.wait_group %0;" :: "n"(N));
}
__device__ __forceinline__ void mbar_init(uint32_t a, uint32_t n) {
    asm volatile("mbarrier.init.shared.b64 [%0], %1;" :: "r"(a), "r"(n) : "memory");
}
__device__ __forceinline__ void mbar_expect_tx(uint32_t a, uint32_t tx) {
    asm volatile("mbarrier.arrive.expect_tx.shared.b64 _, [%0], %1;" :: "r"(a), "r"(tx) : "memory");
}
__device__ __forceinline__ void mbar_wait(uint32_t a, int p) {
    asm volatile(
        "{\n\t.reg .pred P;\n\tWL_%=:\n\t"
        "mbarrier.try_wait.parity.acquire.cta.shared::cta.b64 P, [%0], %1, 0x989680;\n\t"
        "@P bra WD_%=;\n\tbra WL_%=;\n\tWD_%=:\n\t}" :: "r"(a), "r"(p) : "memory");
}
__device__ __forceinline__ void bulk_g2s(uint32_t d, const void* s, uint32_t n, uint32_t mb) {
    asm volatile("cp.async.bulk.shared::cta.global.mbarrier::complete_tx::bytes [%0], [%1], %2, [%3];"
                 :: "r"(d), "l"(s), "r"(n), "r"(mb) : "memory");
}

__device__ __forceinline__ void grid_barrier() {
    __syncthreads();
    if (threadIdx.x == 0) {
        unsigned gen = g_bar_gen;
        __threadfence();
        if (atomicAdd(&g_bar_count, 1u) == gridDim.x - 1) {
            g_bar_count = 0;
            __threadfence();
            g_bar_gen = gen + 1;
        } else {
            while (g_bar_gen == gen) { }
        }
        __threadfence();
    }
    __syncthreads();
}

// ---------- bulk-pipelined split-bf16 mma pass: encoder (16 j-cols) --------
__device__ __forceinline__ void mma_pass_enc(
    const char* __restrict__ Ah, const char* __restrict__ Al,
    const char* __restrict__ Wh, const char* __restrict__ Wl,
    uint32_t sm, uint32_t mb, int stph[3], float acc[3][2][4])
{
    const int tid = threadIdx.x, lane = tid & 31;
    const int m0 = (tid >> 5) * 16;
    const int arow = m0 + (lane & 15);
    const int au_off = (lane >> 4);
    const int brow_lo = (lane & 7) + ((lane >> 4) << 3);
    const int bu_off = ((lane >> 3) & 1);

    if (tid == 0) {
#pragma unroll
        for (int c = 0; c < 3; c++) {
            uint32_t bar = mb + c * 8, base = sm + c * STG_E;
            mbar_expect_tx(bar, STG_E);
            bulk_g2s(base,                  Ah + (long)c * ACH, ACH, bar);
            bulk_g2s(base + ACH,            Al + (long)c * ACH, ACH, bar);
            bulk_g2s(base + 2 * ACH,        Wh + (long)c * WCHE, WCHE, bar);
            bulk_g2s(base + 2 * ACH + WCHE, Wl + (long)c * WCHE, WCHE, bar);
        }
    }
#pragma unroll 1
    for (int c = 0; c < 16; c++) {
        const int s = c % 3;
        mbar_wait(mb + s * 8, stph[s]);
        stph[s] ^= 1;
        const uint32_t base = sm + s * STG_E;
#pragma unroll
        for (int it = 0; it < 4; it++) {
            uint32_t a_hi[4], a_lo[4];
            int u = it * 2 + au_off;
            uint32_t aaddr = base + arow * 128 + ((u ^ (arow & 7)) * 16);
            ldsm4(a_hi, aaddr);
            ldsm4(a_lo, aaddr + ACH);
#pragma unroll
            for (int g = 0; g < 3; g++) {
                int row = g * 16 + brow_lo;
                int ub = it * 2 + bu_off;
                uint32_t baddr = base + 2 * ACH + row * 128 + ((ub ^ (row & 7)) * 16);
                uint32_t bh4[4], bl4[4];
                ldsm4(bh4, baddr);
                ldsm4(bl4, baddr + WCHE);
                mma16816(acc[g][0], a_hi, bh4);
                mma16816(acc[g][0], a_hi, bl4);
                mma16816(acc[g][0], a_lo, bh4);
                mma16816(acc[g][1], a_hi, bh4 + 2);
                mma16816(acc[g][1], a_hi, bl4 + 2);
                mma16816(acc[g][1], a_lo, bh4 + 2);
            }
        }
        __syncthreads();
        if (tid == 0 && c + 3 < 16) {
            int cn = c + 3;
            uint32_t bar = mb + s * 8, base2 = sm + s * STG_E;
            mbar_expect_tx(bar, STG_E);
            bulk_g2s(base2,                  Ah + (long)cn * ACH, ACH, bar);
            bulk_g2s(base2 + ACH,            Al + (long)cn * ACH, ACH, bar);
            bulk_g2s(base2 + 2 * ACH,        Wh + (long)cn * WCHE, WCHE, bar);
            bulk_g2s(base2 + 2 * ACH + WCHE, Wl + (long)cn * WCHE, WCHE, bar);
        }
    }
}

// ---------- bulk-pipelined split-bf16 mma pass: decoder (8 j-cols) ---------
__device__ __forceinline__ void mma_pass_dec(
    const char* __restrict__ Ah, const char* __restrict__ Al,
    const char* __restrict__ Wh, const char* __restrict__ Wl,
    uint32_t sm, uint32_t mb, int stph[2], float acc[3][4])
{
    const int tid = threadIdx.x, lane = tid & 31;
    const int m0 = (tid >> 5) * 16;
    const int arow = m0 + (lane & 15);
    const int au_off = (lane >> 4);
    const int brow_lo = (lane & 7) + ((lane >> 4) << 3);
    const int bu_off = ((lane >> 3) & 1);
    const int row2 = 16 + (lane & 7);
    const int bu2 = ((lane >> 3) & 1);

    if (tid == 0) {
#pragma unroll
        for (int c = 0; c < 2; c++) {
            uint32_t bar = mb + c * 8, base = sm + c * STG_D;
            mbar_expect_tx(bar, STG_D);
            bulk_g2s(base,                  Ah + (long)c * ACH, ACH, bar);
            bulk_g2s(base + ACH,            Al + (long)c * ACH, ACH, bar);
            bulk_g2s(base + 2 * ACH,        Wh + (long)c * WCHD, WCHD, bar);
            bulk_g2s(base + 2 * ACH + WCHD, Wl + (long)c * WCHD, WCHD, bar);
        }
    }
#pragma unroll 1
    for (int c = 0; c < 16; c++) {
        const int s = c & 1;
        mbar_wait(mb + s * 8, stph[s]);
        stph[s] ^= 1;
        const uint32_t base = sm + s * STG_D;
#pragma unroll
        for (int it = 0; it < 4; it++) {
            uint32_t a_hi[4], a_lo[4];
            int u = it * 2 + au_off;
            uint32_t aaddr = base + arow * 128 + ((u ^ (arow & 7)) * 16);
            ldsm4(a_hi, aaddr);
            ldsm4(a_lo, aaddr + ACH);
            {
                int row = brow_lo;
                int ub = it * 2 + bu_off;
                uint32_t baddr = base + 2 * ACH + row * 128 + ((ub ^ (row & 7)) * 16);
                uint32_t bh4[4], bl4[4];
                ldsm4(bh4, baddr);
                ldsm4(bl4, baddr + WCHD);
                mma16816(acc[0], a_hi, bh4);
                mma16816(acc[0], a_hi, bl4);
                mma16816(acc[0], a_lo, bh4);
                mma16816(acc[1], a_hi, bh4 + 2);
                mma16816(acc[1], a_hi, bl4 + 2);
                mma16816(acc[1], a_lo, bh4 + 2);
            }
            {
                int ub = it * 2 + bu2;
                uint32_t baddr = base + 2 * ACH + row2 * 128 + ((ub ^ (row2 & 7)) * 16);
                uint32_t b2h[2], b2l[2];
                ldsm2(b2h, baddr);
                ldsm2(b2l, baddr + WCHD);
                mma16816(acc[2], a_hi, b2h);
                mma16816(acc[2], a_hi, b2l);
                mma16816(acc[2], a_lo, b2h);
            }
        }
        __syncthreads();
        if (tid == 0 && c + 2 < 16) {
            int cn = c + 2;
            int sn = cn & 1;
            uint32_t bar = mb + sn * 8, base2 = sm + sn * STG_D;
            mbar_expect_tx(bar, STG_D);
            bulk_g2s(base2,                  Ah + (long)cn * ACH, ACH, bar);
            bulk_g2s(base2 + ACH,            Al + (long)cn * ACH, ACH, bar);
            bulk_g2s(base2 + 2 * ACH,        Wh + (long)cn * WCHD, WCHD, bar);
            bulk_g2s(base2 + 2 * ACH + WCHD, Wl + (long)cn * WCHD, WCHD, bar);
        }
    }
}

__device__ __forceinline__ void store_chunked(bf16* hi, bf16* lo, int m, int jj,
                                              float v0, float v1) {
    int cb = jj >> 6, wcol = jj & 63;
    int up = (wcol >> 3) ^ (m & 7);
    long off = (long)cb * 8192 + m * 64 + up * 8 + (wcol & 7);
    bf16 h0 = __float2bfloat16(v0);
    bf16 h1 = __float2bfloat16(v1);
    *(__nv_bfloat162*)(hi + off) = __nv_bfloat162(h0, h1);
    *(__nv_bfloat162*)(lo + off) = __nv_bfloat162(
        __float2bfloat16(v0 - __bfloat162float(h0)),
        __float2bfloat16(v1 - __bfloat162float(h1)));
}

// -------------------- persistent encoder (bidirectional GRU) ---------------
__global__ void __launch_bounds__(256, 1)
encoder_kernel(const float* __restrict__ bh_f, const float* __restrict__ bh_b) {
    extern __shared__ __align__(16) char smem[];
    uint32_t sm = (uint32_t)__cvta_generic_to_shared(smem);
    uint32_t mb = sm + 3 * STG_E;
    const int tid = threadIdx.x, lane = tid & 31;
    const int m0 = (tid >> 5) * 16;
    const int dir = blockIdx.x >> 6;
    const int jt = blockIdx.x & 63;
    const int j0 = jt * 16;

    if (tid == 0) { mbar_init(mb, 1); mbar_init(mb + 8, 1); mbar_init(mb + 16, 1); }
    __syncthreads();
    int stph[3] = {0, 0, 0};

    const char* Wh = (const char*)(dir ? g_whhb_hi : g_whhf_hi) + (long)jt * WTILE_E;
    const char* Wl = (const char*)(dir ? g_whhb_lo : g_whhf_lo) + (long)jt * WTILE_E;
    const float* gi = dir ? g_gib : g_gif;
    const float* bh = dir ? bh_b : bh_f;

    float bh2[2][6];
#pragma unroll
    for (int ct = 0; ct < 2; ct++) {
        int jj = j0 + ct * 8 + (lane & 3) * 2;
#pragma unroll
        for (int g = 0; g < 3; g++) {
            bh2[ct][g * 2]     = bh[g * H_ + jj];
            bh2[ct][g * 2 + 1] = bh[g * H_ + jj + 1];
        }
    }

#pragma unroll 1
    for (int t = 0; t < T_; t++) {
        const int cur = t & 1, nxt = cur ^ 1;
        const char* Ah = (const char*)(dir ? g_hbc_hi[cur] : g_hfc_hi[cur]);
        const char* Al = (const char*)(dir ? g_hbc_lo[cur] : g_hfc_lo[cur]);
        const float* hc = dir ? g_hb[cur] : g_hf[cur];
        float*       hn = dir ? g_hb[nxt] : g_hf[nxt];
        bf16* chi = dir ? g_hbc_hi[nxt] : g_hfc_hi[nxt];
        bf16* clo = dir ? g_hbc_lo[nxt] : g_hfc_lo[nxt];
        const int tstep = dir ? (T_ - 1 - t) : t;

        float acc[3][2][4] = {};
        mma_pass_enc(Ah, Al, Wh, Wl, sm, mb, stph, acc);

#pragma unroll
        for (int ct = 0; ct < 2; ct++) {
            int jj = j0 + ct * 8 + (lane & 3) * 2;
#pragma unroll
            for (int half = 0; half < 2; half++) {
                int m = m0 + (lane >> 2) + half * 8;
                long gb = ((long)m * T_ + tstep) * H3_ + jj;
                float2 gr = *(const float2*)(gi + gb);
                float2 gz = *(const float2*)(gi + gb + H_);
                float2 gn = *(const float2*)(gi + gb + 2 * H_);
                float2 hp = *(const float2*)(hc + (long)m * H_ + jj);
                float r0 = sigmoidf_(gr.x + acc[0][ct][half * 2]     + bh2[ct][0]);
                float r1 = sigmoidf_(gr.y + acc[0][ct][half * 2 + 1] + bh2[ct][1]);
                float u0 = sigmoidf_(gz.x + acc[1][ct][half * 2]     + bh2[ct][2]);
                float u1 = sigmoidf_(gz.y + acc[1][ct][half * 2 + 1] + bh2[ct][3]);
                float n0 = tanhf(gn.x + r0 * (acc[2][ct][half * 2]     + bh2[ct][4]));
                float n1 = tanhf(gn.y + r1 * (acc[2][ct][half * 2 + 1] + bh2[ct][5]));
                float v0 = (1.f - u0) * n0 + u0 * hp.x;
                float v1 = (1.f - u1) * n1 + u1 * hp.y;
                *(float2*)(hn + (long)m * H_ + jj) = make_float2(v0, v1);
                store_chunked(chi, clo, m, jj, v0, v1);
            }
        }
        grid_barrier();
    }
}

// ---------- persistent decoder: software-pipelined, 1 barrier/window -------
// 256 CTAs, 2/SM. Window k (k=0..T):
//   role0 (bid<128): phaseA(k) for k<T      [h0(k) -> h0(k+1)]
//   role1 (bid>=128): step s=k-1 tail for k>=1: accH(s) + accI(s) + epiB(s)
// Single grid barrier per window; accH/accI stay in registers.
__global__ void __launch_bounds__(256, 2)
decoder_kernel(const float* __restrict__ b_hh_g,
               const float* __restrict__ b_ih_g2, const float* __restrict__ b_hh_g2) {
    extern __shared__ __align__(16) char smem[];
    uint32_t sm = (uint32_t)__cvta_generic_to_shared(smem);
    uint32_t mb = sm + 2 * STG_D;
    const int tid = threadIdx.x, lane = tid & 31;
    const int m0 = (tid >> 5) * 16;
    const bool role0 = blockIdx.x < 128;
    const int jt = blockIdx.x & 127;
    const int j0 = jt * 8;
    const int jj = j0 + (lane & 3) * 2;

    if (tid == 0) { mbar_init(mb, 1); mbar_init(mb + 8, 1); }
    __syncthreads();
    int stph[2] = {0, 0};

    const char* Wg_h = (const char*)g_whhg_hi  + (long)jt * WTILE_D;
    const char* Wg_l = (const char*)g_whhg_lo  + (long)jt * WTILE_D;
    const char* Wi_h = (const char*)g_wihg2_hi + (long)jt * WTILE_D;
    const char* Wi_l = (const char*)g_wihg2_lo + (long)jt * WTILE_D;
    const char* Wh_h = (const char*)g_whhg2_hi + (long)jt * WTILE_D;
    const char* Wh_l = (const char*)g_whhg2_lo + (long)jt * WTILE_D;

    float bg6[6], bi6[6], bh6[6];
#pragma unroll
    for (int g = 0; g < 3; g++) {
        bg6[g * 2] = b_hh_g[g * H_ + jj];   bg6[g * 2 + 1] = b_hh_g[g * H_ + jj + 1];
        bi6[g * 2] = b_ih_g2[g * H_ + jj];  bi6[g * 2 + 1] = b_ih_g2[g * H_ + jj + 1];
        bh6[g * 2] = b_hh_g2[g * H_ + jj];  bh6[g * 2 + 1] = b_hh_g2[g * H_ + jj + 1];
    }

#pragma unroll 1
    for (int k = 0; k <= T_; k++) {
        if (role0) {
            if (k < T_) {
                const int cur = k & 1, nxt = cur ^ 1;
                float acc[3][4] = {};
                mma_pass_dec((const char*)g_h0c_hi[cur], (const char*)g_h0c_lo[cur],
                             Wg_h, Wg_l, sm, mb, stph, acc);
#pragma unroll
                for (int half = 0; half < 2; half++) {
                    int m = m0 + (lane >> 2) + half * 8;
                    long gb = ((long)m * T_ + k) * H3_ + jj;
                    long zb = (long)m * H3_ + jj;
                    float2 gr = *(const float2*)(g_gid + gb);
                    float2 gz = *(const float2*)(g_gid + gb + H_);
                    float2 gn = *(const float2*)(g_gid + gb + 2 * H_);
                    float2 zr = *(const float2*)(g_zi + zb);
                    float2 zz = *(const float2*)(g_zi + zb + H_);
                    float2 zn = *(const float2*)(g_zi + zb + 2 * H_);
                    float2 hp = *(const float2*)(g_h0[cur] + (long)m * H_ + jj);
                    float r0 = sigmoidf_(gr.x + zr.x + acc[0][half * 2]     + bg6[0]);
                    float r1 = sigmoidf_(gr.y + zr.y + acc[0][half * 2 + 1] + bg6[1]);
                    float u0 = sigmoidf_(gz.x + zz.x + acc[1][half * 2]     + bg6[2]);
                    float u1 = sigmoidf_(gz.y + zz.y + acc[1][half * 2 + 1] + bg6[3]);
                    float n0 = tanhf(gn.x + zn.x + r0 * (acc[2][half * 2]     + bg6[4]));
                    float n1 = tanhf(gn.y + zn.y + r1 * (acc[2][half * 2 + 1] + bg6[5]));
                    float v0 = (1.f - u0) * n0 + u0 * hp.x;
                    float v1 = (1.f - u1) * n1 + u1 * hp.y;
                    *(float2*)(g_h0[nxt] + (long)m * H_ + jj) = make_float2(v0, v1);
                    store_chunked(g_h0c_hi[nxt], g_h0c_lo[nxt], m, jj, v0, v1);
                }
            }
        } else if (k >= 1) {
            const int s = k - 1;
            const int scur = s & 1, snxt = scur ^ 1;
            // h1(s): epiB(s-1) output in g_h1c[scur]; at s=0, h1p = h0n(0) = g_h0c[1]
            const char* h1p_hi = (s == 0) ? (const char*)g_h0c_hi[1] : (const char*)g_h1c_hi[scur];
            const char* h1p_lo = (s == 0) ? (const char*)g_h0c_lo[1] : (const char*)g_h1c_lo[scur];
            const float* h1p_f = (s == 0) ? g_h0[1] : g_h1[scur];

            float accH[3][4] = {};
            float accI[3][4] = {};
            mma_pass_dec(h1p_hi, h1p_lo, Wh_h, Wh_l, sm, mb, stph, accH);
            mma_pass_dec((const char*)g_h0c_hi[snxt], (const char*)g_h0c_lo[snxt],
                         Wi_h, Wi_l, sm, mb, stph, accI);
#pragma unroll
            for (int half = 0; half < 2; half++) {
                int m = m0 + (lane >> 2) + half * 8;
                float2 hp = *(const float2*)(h1p_f + (long)m * H_ + jj);
                float r0 = sigmoidf_((accI[0][half * 2]     + bi6[0]) + (accH[0][half * 2]     + bh6[0]));
                float r1 = sigmoidf_((accI[0][half * 2 + 1] + bi6[1]) + (accH[0][half * 2 + 1] + bh6[1]));
                float u0 = sigmoidf_((accI[1][half * 2]     + bi6[2]) + (accH[1][half * 2]     + bh6[2]));
                float u1 = sigmoidf_((accI[1][half * 2 + 1] + bi6[3]) + (accH[1][half * 2 + 1] + bh6[3]));
                float n0 = tanhf((accI[2][half * 2]     + bi6[4]) + r0 * (accH[2][half * 2]     + bh6[4]));
                float n1 = tanhf((accI[2][half * 2 + 1] + bi6[5]) + r1 * (accH[2][half * 2 + 1] + bh6[5]));
                float v0 = (1.f - u0) * n0 + u0 * hp.x;
                float v1 = (1.f - u1) * n1 + u1 * hp.y;
                *(float2*)(g_h1[snxt] + (long)m * H_ + jj) = make_float2(v0, v1);
                store_chunked(g_h1c_hi[snxt], g_h1c_lo[snxt], m, jj, v0, v1);
                bf16 h0b = __float2bfloat16(v0);
                bf16 h1b = __float2bfloat16(v1);
                long ho = ((long)m * T_ + s) * H_ + jj;
                *(__nv_bfloat162*)(g_h1a_hi + ho) = __nv_bfloat162(h0b, h1b);
                *(__nv_bfloat162*)(g_h1a_lo + ho) = __nv_bfloat162(
                    __float2bfloat16(v0 - __bfloat162float(h0b)),
                    __float2bfloat16(v1 - __bfloat162float(h1b)));
            }
        }
        grid_barrier();
    }
}

// ------------------- split-bf16 batched GEMM (mma.sync) ---------------------
struct BfArgs {
    const bf16 *Ah, *Al, *Wh, *Wl;
    const float* bias;
    float* C;
    long lda, ldb, ldc;
    int  N, kchunks;
};

__global__ void __launch_bounds__(256, 2) gemm_bf16_kernel(BfArgs a) {
    extern __shared__ char smem[];
    uint32_t sm = (uint32_t)__cvta_generic_to_shared(smem);
    const long bm = (long)blockIdx.y * 128;
    const int  bn = blockIdx.x * 64;
    const int tid = threadIdx.x, lane = tid & 31;
    const int m0 = (tid >> 5) * 16;
    const int arow  = m0 + (lane & 15);
    const int ahalf = (lane >> 4) * 16;
    const int brow  = lane & 7;
    const int bhalf = ((lane >> 3) & 1) * 16;

    float acc[8][4];
#pragma unroll
    for (int nt = 0; nt < 8; nt++)
#pragma unroll
        for (int q = 0; q < 4; q++) acc[nt][q] = 0.f;

    auto issue = [&](int c, int st) {
        uint32_t base = sm + st * STAGE_G;
        long k0 = (long)c * KCH;
#pragma unroll
        for (int i = 0; i < 8; i++) {
            int u = tid + i * 256;
            int mat = u >= 1024; int r = mat ? u - 1024 : u;
            int row = r >> 3, seg = r & 7;
            cpa16(base + (mat ? ABYTES : 0) + row * ROWB + seg * 16,
                  (mat ? a.Al : a.Ah) + (bm + row) * a.lda + k0 + seg * 8);
        }
#pragma unroll
        for (int i = 0; i < 4; i++) {
            int u = tid + i * 256;
            int mat = u >= 512; int r = mat ? u - 512 : u;
            int row = r >> 3, seg = r & 7;
            cpa16(base + 2 * ABYTES + (mat ? BBYT_G : 0) + row * ROWB + seg * 16,
                  (mat ? a.Wl : a.Wh) + (long)(bn + row) * a.ldb + k0 + seg * 8);
        }
    };

    issue(0, 0); cp_commit();
#pragma unroll 1
    for (int c = 0; c < a.kchunks; c++) {
        if (c < a.kchunks - 1) { issue(c + 1, (c + 1) & 1); cp_commit(); cp_wait<1>(); }
        else                   { cp_wait<0>(); }
        __syncthreads();
        uint32_t base = sm + (c & 1) * STAGE_G;
#pragma unroll
        for (int s = 0; s < 4; s++) {
            uint32_t aoff = base + arow * ROWB + ahalf + s * 32;
            uint32_t a_hi[4], a_lo[4];
            ldsm4(a_hi, aoff);
            ldsm4(a_lo, aoff + ABYTES);
#pragma unroll
            for (int nt = 0; nt < 8; nt++) {
                uint32_t boff = base + 2 * ABYTES + (nt * 8 + brow) * ROWB + bhalf + s * 32;
                uint32_t b_hi[2], b_lo[2];
                ldsm2(b_hi, boff);
                ldsm2(b_lo, boff + BBYT_G);
                mma16816(acc[nt], a_hi, b_hi);
                mma16816(acc[nt], a_hi, b_lo);
                mma16816(acc[nt], a_lo, b_hi);
            }
        }
        __syncthreads();
    }

#pragma unroll
    for (int nt = 0; nt < 8; nt++) {
        int gn = bn + nt * 8 + (lane & 3) * 2;
        float b0 = 0.f, b1 = 0.f;
        if (a.bias) {
            if (gn < a.N)     b0 = a.bias[gn];
            if (gn + 1 < a.N) b1 = a.bias[gn + 1];
        }
#pragma unroll
        for (int half = 0; half < 2; half++) {
            long m = bm + m0 + (lane >> 2) + half * 8;
            if (gn < a.N)     a.C[m * a.ldc + gn]     = acc[nt][half * 2]     + b0;
            if (gn + 1 < a.N) a.C[m * a.ldc + gn + 1] = acc[nt][half * 2 + 1] + b1;
        }
    }
}

// ------------------------------- fp32 GEMM ----------------------------------
struct GArgs {
    const float* A;  long lda;
    const float* W;  long ldw;
    const float* bias;
    float*       C;  long ldc;
    int M, N, K;
};
constexpr int GBM = 128, GBN = 128, GBK = 16;

__global__ void __launch_bounds__(256, 2) gemm_nt_kernel(GArgs g0, GArgs g1) {
    GArgs g = (blockIdx.z == 0) ? g0 : g1;
    const int bm = blockIdx.y * GBM;
    const int bn = blockIdx.x * GBN;
    if (bm >= g.M || bn >= g.N) return;
    __shared__ float As[GBK][GBM + 4];
    __shared__ ull   Bs[GBK][GBN + 1];
    const int tid = threadIdx.x;
    const int tx  = tid & 15, ty = tid >> 4;
    const int r0  = ty * 8;

    ull acc[4][8];
#pragma unroll
    for (int p = 0; p < 4; p++)
#pragma unroll
        for (int c = 0; c < 8; c++) acc[p][c] = 0ull;

    for (int k0 = 0; k0 < g.K; k0 += GBK) {
#pragma unroll
        for (int i = 0; i < 8; i++) {
            int idx = tid + i * 256;
            int m = idx >> 4, kk = idx & 15;
            int gm = bm + m, gk = k0 + kk;
            float v = 0.f;
            if (gm < g.M && gk < g.K) v = g.A[(long)gm * g.lda + gk];
            As[kk][m] = v;
        }
#pragma unroll
        for (int i = 0; i < 8; i++) {
            int idx = tid + i * 256;
            int n = idx >> 4, kk = idx & 15;
            int gn = bn + n, gk = k0 + kk;
            float v = 0.f;
            if (gn < g.N && gk < g.K) v = g.W[(long)gn * g.ldw + gk];
            Bs[kk][(n & 7) * 16 + (n >> 3)] = pack2(v, v);
        }
        __syncthreads();
#pragma unroll
        for (int kk = 0; kk < GBK; kk++) {
            ull a[4], b[8];
#pragma unroll
            for (int p = 0; p < 4; p++) a[p] = *(const ull*)&As[kk][r0 + 2 * p];
#pragma unroll
            for (int c = 0; c < 8; c++) b[c] = Bs[kk][c * 16 + tx];
#pragma unroll
            for (int p = 0; p < 4; p++)
#pragma unroll
                for (int c = 0; c < 8; c++) fma2(acc[p][c], a[p], b[c]);
        }
        __syncthreads();
    }
#pragma unroll
    for (int p = 0; p < 4; p++) {
        int gm = bm + r0 + 2 * p;
#pragma unroll
        for (int c = 0; c < 8; c++) {
            int gn = bn + tx * 8 + c;
            if (gn >= g.N) continue;
            float2 v = unpack2(acc[p][c]);
            float bias = g.bias ? g.bias[gn] : 0.f;
            if (gm < g.M)     g.C[(long)gm * g.ldc + gn]       = v.x + bias;
            if (gm + 1 < g.M) g.C[(long)(gm + 1) * g.ldc + gn] = v.y + bias;
        }
    }
}

// --------------------------- elementwise kernels ----------------------------
__global__ void init_kernel(const float* __restrict__ x) {
    long stride = (long)gridDim.x * blockDim.x;
    long i0 = (long)blockIdx.x * blockDim.x + threadIdx.x;
    if (i0 == 0) { g_bar_count = 0; g_bar_gen = 0; }
    for (long i = i0; i < BH_; i += stride) {
        g_hf[0][i] = 0.f; g_hb[0][i] = 0.f;
        g_hfc_hi[0][i] = bf16(0.f); g_hfc_lo[0][i] = bf16(0.f);
        g_hbc_hi[0][i] = bf16(0.f); g_hbc_lo[0][i] = bf16(0.f);
    }
    for (long i = i0; i < BT_ * R_; i += stride) {
        int  r = (int)(i % R_);
        long m = i / R_;
        int  t = (int)(m % T_);
        g_decin[i] = (t == 0) ? ((r == R_ - 1) ? 1.f : 0.f) : x[i - R_];
    }
}

// W [3H x H] -> [64 jt][16 c][48 rows x 128B] chunk-swizzled (encoder)
__global__ void convert_w_tiled_enc(const float* __restrict__ src,
                                    bf16* __restrict__ hi, bf16* __restrict__ lo) {
    long stride = (long)gridDim.x * blockDim.x;
    for (long q = (long)blockIdx.x * blockDim.x + threadIdx.x; q < 393216; q += stride) {
        int up = (int)(q & 7);
        long r = q >> 3;
        int rw = (int)(r % 48);
        long rc = r / 48;
        int c = (int)(rc & 15);
        int jt = (int)(rc >> 4);
        int u = up ^ (rw & 7);
        int g = rw >> 4;
        int j = jt * 16 + (rw & 15);
        int k = c * 64 + u * 8;
        const float* s = src + (long)(g * H_ + j) * H_ + k;
        bf16 h8[8], l8[8];
#pragma unroll
        for (int e = 0; e < 8; e++) {
            float w = s[e];
            bf16 h = __float2bfloat16(w);
            h8[e] = h;
            l8[e] = __float2bfloat16(w - __bfloat162float(h));
        }
        *(uint4*)(hi + q * 8) = *(uint4*)h8;
        *(uint4*)(lo + q * 8) = *(uint4*)l8;
    }
}

// W [3H x H] -> [128 jt][16 c][24 rows x 128B] chunk-swizzled (decoder)
__global__ void convert_w_tiled_dec(const float* __restrict__ src,
                                    bf16* __restrict__ hi, bf16* __restrict__ lo) {
    long stride = (long)gridDim.x * blockDim.x;
    for (long q = (long)blockIdx.x * blockDim.x + threadIdx.x; q < 393216; q += stride) {
        int up = (int)(q & 7);
        long r = q >> 3;
        int rw = (int)(r % 24);
        long rc = r / 24;
        int c = (int)(rc & 15);
        int jt = (int)(rc >> 4);
        int u = up ^ (rw & 7);
        int g = rw >> 3;
        int j = jt * 8 + (rw & 7);
        int k = c * 64 + u * 8;
        const float* s = src + (long)(g * H_ + j) * H_ + k;
        bf16 h8[8], l8[8];
#pragma unroll
        for (int e = 0; e < 8; e++) {
            float w = s[e];
            bf16 h = __float2bfloat16(w);
            h8[e] = h;
            l8[e] = __float2bfloat16(w - __bfloat162float(h));
        }
        *(uint4*)(hi + q * 8) = *(uint4*)h8;
        *(uint4*)(lo + q * 8) = *(uint4*)l8;
    }
}

__global__ void convert_h_chunked(const float* __restrict__ src,
                                  bf16* __restrict__ hi, bf16* __restrict__ lo) {
    long stride = (long)gridDim.x * blockDim.x;
    for (long q = (long)blockIdx.x * blockDim.x + threadIdx.x; q < 16384; q += stride) {
        int up = (int)(q & 7);
        int row = (int)((q >> 3) & 127);
        int c = (int)(q >> 10);
        int u = up ^ (row & 7);
        int k = c * 64 + u * 8;
        const float* s = src + (long)row * H_ + k;
        bf16 h8[8], l8[8];
#pragma unroll
        for (int e = 0; e < 8; e++) {
            float w = s[e];
            bf16 h = __float2bfloat16(w);
            h8[e] = h;
            l8[e] = __float2bfloat16(w - __bfloat162float(h));
        }
        *(uint4*)(hi + q * 8) = *(uint4*)h8;
        *(uint4*)(lo + q * 8) = *(uint4*)l8;
    }
}

__global__ void convert_pad_kernel(const float* __restrict__ src, long srcld,
                                   long srcrows, int cols, long dstld, long rows,
                                   bf16* __restrict__ hi, bf16* __restrict__ lo) {
    long stride = (long)gridDim.x * blockDim.x;
    long total = rows * dstld;
    for (long i = (long)blockIdx.x * blockDim.x + threadIdx.x; i < total; i += stride) {
        long r = i / dstld;
        long c = i - r * dstld;
        float v = (r < srcrows && c < cols) ? src[r * srcld + c] : 0.f;
        bf16 h = __float2bfloat16(v);
        hi[i] = h;
        lo[i] = __float2bfloat16(v - __bfloat162float(h));
    }
}

__global__ void henc_kernel() {
    int i = blockIdx.x * blockDim.x + threadIdx.x;
    if (i >= B_ * H_) return;
    int b = i / H_, jj = i % H_;
    g_henc[(long)b * 2 * H_ + jj]      = g_hf[0][i];
    g_henc[(long)b * 2 * H_ + H_ + jj] = g_hb[0][i];
}

__global__ void zstd_kernel(const float* __restrict__ eps,
                            const float* __restrict__ chroma,
                            const float* __restrict__ mu_out,
                            float* __restrict__ std_out,
                            float* __restrict__ z_out) {
    int b = blockIdx.x;
    int jj = threadIdx.x;
    if (jj < Z2_) {
        float mu = mu_out[(long)b * Z2_ + jj];
        float sd = expf(g_var[(long)b * Z2_ + jj]);
        float z  = mu + sd * eps[(long)b * Z2_ + jj];
        std_out[(long)b * Z2_ + jj] = sd;
        z_out[(long)b * ZC_ + jj]   = z;
        g_zbuf[(long)b * ZC_ + jj]  = z;
    } else if (jj < ZC_) {
        float cv = chroma[(long)b * C_ + (jj - Z2_)];
        z_out[(long)b * ZC_ + jj]  = cv;
        g_zbuf[(long)b * ZC_ + jj] = cv;
    }
}

__global__ void logsoftmax_kernel(const float* __restrict__ logits,
                                  float* __restrict__ out) {
    long warp = ((long)blockIdx.x * blockDim.x + threadIdx.x) >> 5;
    int  lane = threadIdx.x & 31;
    if (warp >= BT_) return;
    const float* row = logits + warp * R_;
    float mx = -1e30f;
    for (int jj = lane; jj < R_; jj += 32) mx = fmaxf(mx, row[jj]);
#pragma unroll
    for (int o = 16; o; o >>= 1) mx = fmaxf(mx, __shfl_xor_sync(0xffffffff, mx, o));
    float s = 0.f;
    for (int jj = lane; jj < R_; jj += 32) s += expf(row[jj] - mx);
#pragma unroll
    for (int o = 16; o; o >>= 1) s += __shfl_xor_sync(0xffffffff, s, o);
    float lse = mx + logf(s);
    float* orow = out + warp * R_;
    for (int jj = lane; jj < R_; jj += 32) orow[jj] = row[jj] - lse;
}

// ------------------------------ host helpers --------------------------------
static void launch_gemm2(const GArgs& a, const GArgs& b) {
    int M = a.M > b.M ? a.M : b.M;
    int N = a.N > b.N ? a.N : b.N;
    dim3 grid((N + GBN - 1) / GBN, (M + GBM - 1) / GBM, 2);
    gemm_nt_kernel<<<grid, 256>>>(a, b);
}
static void launch_bf_gemm(const BfArgs& a) {
    dim3 grid((a.N + 63) / 64, 32768 / 128, 1);
    gemm_bf16_kernel<<<grid, 256, SMEM_G>>>(a);
}
template <typename Tp>
static float* sym_addr(Tp& sym) {
    void* p = nullptr;
    cudaGetSymbolAddress(&p, sym);
    return (float*)p;
}
template <typename Tp>
static bf16* sym_addr_bf(Tp& sym) {
    void* p = nullptr;
    cudaGetSymbolAddress(&p, sym);
    return (bf16*)p;
}
} // namespace

extern "C" void kernel_launch(void* const* d_in, const int* in_sizes, int n_in,
                              void* d_out, int out_size) {
    (void)in_sizes; (void)n_in; (void)out_size;
    const float* x        = (const float*)d_in[0];
    const float* chroma   = (const float*)d_in[1];
    const float* eps      = (const float*)d_in[2];
    const float* w_ih_f   = (const float*)d_in[3];
    const float* w_hh_f   = (const float*)d_in[4];
    const float* b_ih_f   = (const float*)d_in[5];
    const float* b_hh_f   = (const float*)d_in[6];
    const float* w_ih_b   = (const float*)d_in[7];
    const float* w_hh_b   = (const float*)d_in[8];
    const float* b_ih_b   = (const float*)d_in[9];
    const float* b_hh_b   = (const float*)d_in[10];
    const float* w_mu     = (const float*)d_in[11];
    const float* b_mu     = (const float*)d_in[12];
    const float* w_var    = (const float*)d_in[13];
    const float* b_var    = (const float*)d_in[14];
    const float* w_init   = (const float*)d_in[15];
    const float* b_init   = (const float*)d_in[16];
    const float* w_ih_g   = (const float*)d_in[17];
    const float* w_hh_g   = (const float*)d_in[18];
    const float* b_ih_g   = (const float*)d_in[19];
    const float* b_hh_g   = (const float*)d_in[20];
    const float* w_ih_g2  = (const float*)d_in[21];
    const float* w_hh_g2  = (const float*)d_in[22];
    const float* b_ih_g2  = (const float*)d_in[23];
    const float* b_hh_g2  = (const float*)d_in[24];
    const float* w_out    = (const float*)d_in[25];
    const float* b_out    = (const float*)d_in[26];

    float* out = (float*)d_out;
    const long MU_OFF  = BT_ * R_;
    const long STD_OFF = MU_OFF + (long)B_ * Z2_;
    const long Z_OFF   = STD_OFF + (long)B_ * Z2_;

    float* p_gif   = sym_addr(g_gif);
    float* p_gib   = sym_addr(g_gib);
    float* p_gid   = sym_addr(g_gid);
    float* p_zi    = sym_addr(g_zi);
    float* p_h0    = sym_addr(g_h0);
    float* p_henc  = sym_addr(g_henc);
    float* p_var   = sym_addr(g_var);
    float* p_zbuf  = sym_addr(g_zbuf);
    float* p_decin = sym_addr(g_decin);
    float* p_logit = sym_addr(g_logits);

    cudaFuncSetAttribute(encoder_kernel,   cudaFuncAttributeMaxDynamicSharedMemorySize, SMEM_E);
    cudaFuncSetAttribute(decoder_kernel,   cudaFuncAttributeMaxDynamicSharedMemorySize, SMEM_D2);
    cudaFuncSetAttribute(gemm_bf16_kernel, cudaFuncAttributeMaxDynamicSharedMemorySize, SMEM_G);

    // 1. prologue
    init_kernel<<<512, 256>>>(x);

    // 1b. recurrent weights -> tiled chunk-swizzled split-bf16
    convert_w_tiled_enc<<<512, 256>>>(w_hh_f,  sym_addr_bf(g_whhf_hi),  sym_addr_bf(g_whhf_lo));
    convert_w_tiled_enc<<<512, 256>>>(w_hh_b,  sym_addr_bf(g_whhb_hi),  sym_addr_bf(g_whhb_lo));
    convert_w_tiled_dec<<<512, 256>>>(w_hh_g,  sym_addr_bf(g_whhg_hi),  sym_addr_bf(g_whhg_lo));
    convert_w_tiled_dec<<<512, 256>>>(w_ih_g2, sym_addr_bf(g_wihg2_hi), sym_addr_bf(g_wihg2_lo));
    convert_w_tiled_dec<<<512, 256>>>(w_hh_g2, sym_addr_bf(g_whhg2_hi), sym_addr_bf(g_whhg2_lo));

    // 1c. batched-GEMM operands -> split-bf16 with K padding
    convert_pad_kernel<<<1024, 256>>>(x,       R_,  BT_,  R_,  KPAD, BT_,
                                      sym_addr_bf(g_xc_hi), sym_addr_bf(g_xc_lo));
    convert_pad_kernel<<<1024, 256>>>(p_decin, R_,  BT_,  R_,  KPAD, BT_,
                                      sym_addr_bf(g_dc_hi), sym_addr_bf(g_dc_lo));
    convert_pad_kernel<<<512, 256>>>(w_ih_f,  R_,  H3_,  R_,  KPAD, H3_,
                                     sym_addr_bf(g_wihf_hi), sym_addr_bf(g_wihf_lo));
    convert_pad_kernel<<<512, 256>>>(w_ih_b,  R_,  H3_,  R_,  KPAD, H3_,
                                     sym_addr_bf(g_wihb_hi), sym_addr_bf(g_wihb_lo));
    convert_pad_kernel<<<512, 256>>>(w_ih_g,  410, H3_,  R_,  KPAD, H3_,
                                     sym_addr_bf(g_wihg_hi), sym_addr_bf(g_wihg_lo));
    convert_pad_kernel<<<256, 256>>>(w_out,   H_,  R_,   H_,  H_,   192,
                                     sym_addr_bf(g_wout_hi), sym_addr_bf(g_wout_lo));

    // 2/3. input-gate GEMMs (tensor cores)
    launch_bf_gemm({sym_addr_bf(g_xc_hi), sym_addr_bf(g_xc_lo),
                    sym_addr_bf(g_wihf_hi), sym_addr_bf(g_wihf_lo),
                    b_ih_f, p_gif, KPAD, KPAD, H3_, H3_, KPAD / KCH});
    launch_bf_gemm({sym_addr_bf(g_xc_hi), sym_addr_bf(g_xc_lo),
                    sym_addr_bf(g_wihb_hi), sym_addr_bf(g_wihb_lo),
                    b_ih_b, p_gib, KPAD, KPAD, H3_, H3_, KPAD / KCH});
    launch_bf_gemm({sym_addr_bf(g_dc_hi), sym_addr_bf(g_dc_lo),
                    sym_addr_bf(g_wihg_hi), sym_addr_bf(g_wihg_lo),
                    nullptr, p_gid, KPAD, KPAD, H3_, H3_, KPAD / KCH});

    // 4. persistent bidirectional encoder
    encoder_kernel<<<128, 256, SMEM_E>>>(b_hh_f, b_hh_b);

    // 5. concat final hiddens
    henc_kernel<<<(B_ * H_ + 255) / 256, 256>>>();

    // 6. VAE head
    GArgs gmu {p_henc, 2 * H_, w_mu,  2 * H_, b_mu,  out + MU_OFF, Z2_, B_, Z2_, 2 * H_};
    GArgs gvar{p_henc, 2 * H_, w_var, 2 * H_, b_var, p_var,        Z2_, B_, Z2_, 2 * H_};
    launch_gemm2(gmu, gvar);

    // 7. reparameterize + concat chroma
    zstd_kernel<<<B_, 288>>>(eps, chroma, out + MU_OFF, out + STD_OFF, out + Z_OFF);

    // 8. hx0 + z-part of decoder L1 input gates
    GArgs ghx0{p_zbuf, ZC_, w_init, ZC_, b_init, p_h0, H_, B_, H_, ZC_};
    GArgs gzi {p_zbuf, ZC_, w_ih_g + 130, 410, b_ih_g, p_zi, H3_, B_, H3_, ZC_};
    launch_gemm2(ghx0, gzi);

    // 8b. hx0 -> chunk-swizzled split-bf16
    convert_h_chunked<<<64, 256>>>(p_h0, sym_addr_bf(g_h0c_hi), sym_addr_bf(g_h0c_lo));

    // 9. persistent decoder (software-pipelined, 1 barrier/window)
    decoder_kernel<<<256, 256, SMEM_D2>>>(b_hh_g, b_ih_g2, b_hh_g2);

    // 10. batched output projection
    launch_bf_gemm({sym_addr_bf(g_h1a_hi), sym_addr_bf(g_h1a_lo),
                    sym_addr_bf(g_wout_hi), sym_addr_bf(g_wout_lo),
                    b_out, p_logit, H_, H_, R_, R_, H_ / KCH});

    // 11. log_softmax
    logsoftmax_kernel<<<(int)((BT_ * 32 + 255) / 256), 256>>>(p_logit, out);
}

// round 17
// speedup vs baseline: 1.1226x; 1.1226x over previous
#include <cuda_runtime.h>
#include <cuda_bf16.h>
#include <cuda_fp16.h>
#include <cstdint>
#include <math.h>

namespace {

typedef unsigned long long ull;
typedef __nv_bfloat16 bf16;
typedef __half fp16;

constexpr int  B_  = 128;
constexpr int  T_  = 256;
constexpr int  R_  = 130;
constexpr int  H_  = 1024;
constexpr int  H3_ = 3072;
constexpr int  Z2_ = 256;
constexpr int  C_  = 24;
constexpr int  ZC_ = 280;
constexpr long BT_ = (long)B_ * T_;
constexpr long BH_ = (long)B_ * H_;
constexpr long WN_ = (long)H3_ * H_;
constexpr int  KPAD = 192;

// ---- recurrence pipeline geometry (bulk-copy path) ----
constexpr int ACH   = 16384;              // A chunk bytes per half (128 x 128B)
constexpr int WCHE  = 6144;               // encoder W chunk (48 rows x 128B)
constexpr int WCHD  = 3072;               // decoder W chunk (24 rows x 128B, fp16 single)
constexpr int STG_E = 2 * ACH + 2 * WCHE;
constexpr int STG_D = 2 * ACH + WCHD;     // Ah + Al + W(single fp16)
constexpr int SMEM_E  = 3 * STG_E + 64;   // encoder: 3 stages, 1 CTA/SM
constexpr int SMEM_D2 = 2 * STG_D + 64;   // decoder: 2 stages, 2 CTAs/SM
constexpr long WTILE_E = 16L * WCHE;
constexpr long WTILE_D = 16L * WCHD;      // 49152 B per jt (fp16 single)

// ---- batched-gemm smem geometry (cp.async path) ----
constexpr int KCH     = 64;
constexpr int ROWB    = 144;
constexpr int ABYTES  = 128 * ROWB;
constexpr int BBYT_G  = 64  * ROWB;
constexpr int STAGE_G = 2 * ABYTES + 2 * BBYT_G;
constexpr int SMEM_G  = 2 * STAGE_G;

// ------------------------- device scratch ----------------------------------
__device__ float g_hf[2][B_ * H_];
__device__ float g_hb[2][B_ * H_];
__device__ float g_h0[2][B_ * H_];
__device__ float g_h1[2][B_ * H_];
__device__ bf16 g_hfc_hi[2][B_ * H_], g_hfc_lo[2][B_ * H_];
__device__ bf16 g_hbc_hi[2][B_ * H_], g_hbc_lo[2][B_ * H_];
__device__ fp16 g_h0c_hi[2][B_ * H_], g_h0c_lo[2][B_ * H_];   // decoder: fp16
__device__ fp16 g_h1c_hi[2][B_ * H_], g_h1c_lo[2][B_ * H_];
__device__ bf16 g_whhf_hi[WN_], g_whhf_lo[WN_];   // [64 jt][16 c][48 x 128B]
__device__ bf16 g_whhb_hi[WN_], g_whhb_lo[WN_];
__device__ fp16 g_whhg_f[WN_];                    // decoder W: fp16 single
__device__ fp16 g_wihg2_f[WN_];                   // [128 jt][16 c][24 x 128B]
__device__ fp16 g_whhg2_f[WN_];
__device__ bf16 g_xc_hi[BT_ * KPAD],  g_xc_lo[BT_ * KPAD];
__device__ bf16 g_dc_hi[BT_ * KPAD],  g_dc_lo[BT_ * KPAD];
__device__ bf16 g_wihf_hi[H3_ * KPAD], g_wihf_lo[H3_ * KPAD];
__device__ bf16 g_wihb_hi[H3_ * KPAD], g_wihb_lo[H3_ * KPAD];
__device__ bf16 g_wihg_hi[H3_ * KPAD], g_wihg_lo[H3_ * KPAD];
__device__ bf16 g_wout_hi[192 * H_],  g_wout_lo[192 * H_];
__device__ bf16 g_h1a_hi[BT_ * H_],   g_h1a_lo[BT_ * H_];
__device__ float g_gif[BT_ * H3_];
__device__ float g_gib[BT_ * H3_];
__device__ float g_gid[BT_ * H3_];
__device__ float g_zi [B_ * H3_];
__device__ float g_henc[B_ * 2 * H_];
__device__ float g_var [B_ * Z2_];
__device__ float g_zbuf[B_ * ZC_];
__device__ float g_decin[BT_ * R_];
__device__ float g_logits[BT_ * R_];
__device__ unsigned g_bar_count;
__device__ volatile unsigned g_bar_gen;

// --------------------------- helpers ----------------------------------------
__device__ __forceinline__ ull pack2(float x, float y) {
    ull r; asm("mov.b64 %0, {%1, %2};" : "=l"(r) : "f"(x), "f"(y)); return r;
}
__device__ __forceinline__ float2 unpack2(ull v) {
    float2 f; asm("mov.b64 {%0, %1}, %2;" : "=f"(f.x), "=f"(f.y) : "l"(v)); return f;
}
__device__ __forceinline__ void fma2(ull& d, ull a, ull b) {
    asm("fma.rn.f32x2 %0, %1, %2, %0;" : "+l"(d) : "l"(a), "l"(b));
}
__device__ __forceinline__ float sigmoidf_(float x) { return 1.f / (1.f + expf(-x)); }

__device__ __forceinline__ void ldsm4(uint32_t r[4], uint32_t addr) {
    asm volatile("ldmatrix.sync.aligned.m8n8.x4.shared.b16 {%0,%1,%2,%3}, [%4];"
                 : "=r"(r[0]), "=r"(r[1]), "=r"(r[2]), "=r"(r[3]) : "r"(addr));
}
__device__ __forceinline__ void ldsm2(uint32_t r[2], uint32_t addr) {
    asm volatile("ldmatrix.sync.aligned.m8n8.x2.shared.b16 {%0,%1}, [%2];"
                 : "=r"(r[0]), "=r"(r[1]) : "r"(addr));
}
__device__ __forceinline__ void mma16816(float d[4], const uint32_t a[4], const uint32_t b[2]) {
    asm volatile(
        "mma.sync.aligned.m16n8k16.row.col.f32.bf16.bf16.f32 "
        "{%0,%1,%2,%3}, {%4,%5,%6,%7}, {%8,%9}, {%0,%1,%2,%3};"
        : "+f"(d[0]), "+f"(d[1]), "+f"(d[2]), "+f"(d[3])
        : "r"(a[0]), "r"(a[1]), "r"(a[2]), "r"(a[3]), "r"(b[0]), "r"(b[1]));
}
__device__ __forceinline__ void mma16816h(float d[4], const uint32_t a[4], const uint32_t b[2]) {
    asm volatile(
        "mma.sync.aligned.m16n8k16.row.col.f32.f16.f16.f32 "
        "{%0,%1,%2,%3}, {%4,%5,%6,%7}, {%8,%9}, {%0,%1,%2,%3};"
        : "+f"(d[0]), "+f"(d[1]), "+f"(d[2]), "+f"(d[3])
        : "r"(a[0]), "r"(a[1]), "r"(a[2]), "r"(a[3]), "r"(b[0]), "r"(b[1]));
}
__device__ __forceinline__ void cpa16(uint32_t dst, const void* src) {
    asm volatile("cp.async.cg.shared.global [%0], [%1], 16;" :: "r"(dst), "l"(src));
}
__device__ __forceinline__ void cp_commit() { asm volatile("cp.async.commit_group;"); }
template <int N> __device__ __forceinline__ void cp_wait() {
    asm volatile("cp.async.wait_group %0;" :: "n"(N));
}
__device__ __forceinline__ void mbar_init(uint32_t a, uint32_t n) {
    asm volatile("mbarrier.init.shared.b64 [%0], %1;" :: "r"(a), "r"(n) : "memory");
}
__device__ __forceinline__ void mbar_expect_tx(uint32_t a, uint32_t tx) {
    asm volatile("mbarrier.arrive.expect_tx.shared.b64 _, [%0], %1;" :: "r"(a), "r"(tx) : "memory");
}
__device__ __forceinline__ void mbar_wait(uint32_t a, int p) {
    asm volatile(
        "{\n\t.reg .pred P;\n\tWL_%=:\n\t"
        "mbarrier.try_wait.parity.acquire.cta.shared::cta.b64 P, [%0], %1, 0x989680;\n\t"
        "@P bra WD_%=;\n\tbra WL_%=;\n\tWD_%=:\n\t}" :: "r"(a), "r"(p) : "memory");
}
__device__ __forceinline__ void bulk_g2s(uint32_t d, const void* s, uint32_t n, uint32_t mb) {
    asm volatile("cp.async.bulk.shared::cta.global.mbarrier::complete_tx::bytes [%0], [%1], %2, [%3];"
                 :: "r"(d), "l"(s), "r"(n), "r"(mb) : "memory");
}

__device__ __forceinline__ void grid_barrier() {
    __syncthreads();
    if (threadIdx.x == 0) {
        unsigned gen = g_bar_gen;
        __threadfence();
        if (atomicAdd(&g_bar_count, 1u) == gridDim.x - 1) {
            g_bar_count = 0;
            __threadfence();
            g_bar_gen = gen + 1;
        } else {
            while (g_bar_gen == gen) { }
        }
        __threadfence();
    }
    __syncthreads();
}

// ---------- bulk-pipelined split-bf16 mma pass: encoder (16 j-cols) --------
__device__ __forceinline__ void mma_pass_enc(
    const char* __restrict__ Ah, const char* __restrict__ Al,
    const char* __restrict__ Wh, const char* __restrict__ Wl,
    uint32_t sm, uint32_t mb, int stph[3], float acc[3][2][4])
{
    const int tid = threadIdx.x, lane = tid & 31;
    const int m0 = (tid >> 5) * 16;
    const int arow = m0 + (lane & 15);
    const int au_off = (lane >> 4);
    const int brow_lo = (lane & 7) + ((lane >> 4) << 3);
    const int bu_off = ((lane >> 3) & 1);

    if (tid == 0) {
#pragma unroll
        for (int c = 0; c < 3; c++) {
            uint32_t bar = mb + c * 8, base = sm + c * STG_E;
            mbar_expect_tx(bar, STG_E);
            bulk_g2s(base,                  Ah + (long)c * ACH, ACH, bar);
            bulk_g2s(base + ACH,            Al + (long)c * ACH, ACH, bar);
            bulk_g2s(base + 2 * ACH,        Wh + (long)c * WCHE, WCHE, bar);
            bulk_g2s(base + 2 * ACH + WCHE, Wl + (long)c * WCHE, WCHE, bar);
        }
    }
#pragma unroll 1
    for (int c = 0; c < 16; c++) {
        const int s = c % 3;
        mbar_wait(mb + s * 8, stph[s]);
        stph[s] ^= 1;
        const uint32_t base = sm + s * STG_E;
#pragma unroll
        for (int it = 0; it < 4; it++) {
            uint32_t a_hi[4], a_lo[4];
            int u = it * 2 + au_off;
            uint32_t aaddr = base + arow * 128 + ((u ^ (arow & 7)) * 16);
            ldsm4(a_hi, aaddr);
            ldsm4(a_lo, aaddr + ACH);
#pragma unroll
            for (int g = 0; g < 3; g++) {
                int row = g * 16 + brow_lo;
                int ub = it * 2 + bu_off;
                uint32_t baddr = base + 2 * ACH + row * 128 + ((ub ^ (row & 7)) * 16);
                uint32_t bh4[4], bl4[4];
                ldsm4(bh4, baddr);
                ldsm4(bl4, baddr + WCHE);
                mma16816(acc[g][0], a_hi, bh4);
                mma16816(acc[g][0], a_hi, bl4);
                mma16816(acc[g][0], a_lo, bh4);
                mma16816(acc[g][1], a_hi, bh4 + 2);
                mma16816(acc[g][1], a_hi, bl4 + 2);
                mma16816(acc[g][1], a_lo, bh4 + 2);
            }
        }
        __syncthreads();
        if (tid == 0 && c + 3 < 16) {
            int cn = c + 3;
            uint32_t bar = mb + s * 8, base2 = sm + s * STG_E;
            mbar_expect_tx(bar, STG_E);
            bulk_g2s(base2,                  Ah + (long)cn * ACH, ACH, bar);
            bulk_g2s(base2 + ACH,            Al + (long)cn * ACH, ACH, bar);
            bulk_g2s(base2 + 2 * ACH,        Wh + (long)cn * WCHE, WCHE, bar);
            bulk_g2s(base2 + 2 * ACH + WCHE, Wl + (long)cn * WCHE, WCHE, bar);
        }
    }
}

// ---------- decoder pass: 2-term fp16 (A split hi/lo, W single) -------------
// C tile [128 x 24] = (Ah + Al) @ W^T. 2 stages.
__device__ __forceinline__ void mma_pass_dec(
    const char* __restrict__ Ah, const char* __restrict__ Al,
    const char* __restrict__ W,
    uint32_t sm, uint32_t mb, int stph[2], float acc[3][4])
{
    const int tid = threadIdx.x, lane = tid & 31;
    const int m0 = (tid >> 5) * 16;
    const int arow = m0 + (lane & 15);
    const int au_off = (lane >> 4);
    const int brow_lo = (lane & 7) + ((lane >> 4) << 3);
    const int bu_off = ((lane >> 3) & 1);
    const int row2 = 16 + (lane & 7);
    const int bu2 = ((lane >> 3) & 1);

    if (tid == 0) {
#pragma unroll
        for (int c = 0; c < 2; c++) {
            uint32_t bar = mb + c * 8, base = sm + c * STG_D;
            mbar_expect_tx(bar, STG_D);
            bulk_g2s(base,           Ah + (long)c * ACH, ACH, bar);
            bulk_g2s(base + ACH,     Al + (long)c * ACH, ACH, bar);
            bulk_g2s(base + 2 * ACH, W  + (long)c * WCHD, WCHD, bar);
        }
    }
#pragma unroll 1
    for (int c = 0; c < 16; c++) {
        const int s = c & 1;
        mbar_wait(mb + s * 8, stph[s]);
        stph[s] ^= 1;
        const uint32_t base = sm + s * STG_D;
#pragma unroll
        for (int it = 0; it < 4; it++) {
            uint32_t a_hi[4], a_lo[4];
            int u = it * 2 + au_off;
            uint32_t aaddr = base + arow * 128 + ((u ^ (arow & 7)) * 16);
            ldsm4(a_hi, aaddr);
            ldsm4(a_lo, aaddr + ACH);
            {
                int row = brow_lo;
                int ub = it * 2 + bu_off;
                uint32_t baddr = base + 2 * ACH + row * 128 + ((ub ^ (row & 7)) * 16);
                uint32_t bw4[4];
                ldsm4(bw4, baddr);
                mma16816h(acc[0], a_hi, bw4);
                mma16816h(acc[0], a_lo, bw4);
                mma16816h(acc[1], a_hi, bw4 + 2);
                mma16816h(acc[1], a_lo, bw4 + 2);
            }
            {
                int ub = it * 2 + bu2;
                uint32_t baddr = base + 2 * ACH + row2 * 128 + ((ub ^ (row2 & 7)) * 16);
                uint32_t b2w[2];
                ldsm2(b2w, baddr);
                mma16816h(acc[2], a_hi, b2w);
                mma16816h(acc[2], a_lo, b2w);
            }
        }
        __syncthreads();
        if (tid == 0 && c + 2 < 16) {
            int cn = c + 2;
            int sn = cn & 1;
            uint32_t bar = mb + sn * 8, base2 = sm + sn * STG_D;
            mbar_expect_tx(bar, STG_D);
            bulk_g2s(base2,           Ah + (long)cn * ACH, ACH, bar);
            bulk_g2s(base2 + ACH,     Al + (long)cn * ACH, ACH, bar);
            bulk_g2s(base2 + 2 * ACH, W  + (long)cn * WCHD, WCHD, bar);
        }
    }
}

__device__ __forceinline__ void store_chunked(bf16* hi, bf16* lo, int m, int jj,
                                              float v0, float v1) {
    int cb = jj >> 6, wcol = jj & 63;
    int up = (wcol >> 3) ^ (m & 7);
    long off = (long)cb * 8192 + m * 64 + up * 8 + (wcol & 7);
    bf16 h0 = __float2bfloat16(v0);
    bf16 h1 = __float2bfloat16(v1);
    *(__nv_bfloat162*)(hi + off) = __nv_bfloat162(h0, h1);
    *(__nv_bfloat162*)(lo + off) = __nv_bfloat162(
        __float2bfloat16(v0 - __bfloat162float(h0)),
        __float2bfloat16(v1 - __bfloat162float(h1)));
}

__device__ __forceinline__ void store_chunked_f16(fp16* hi, fp16* lo, int m, int jj,
                                                  float v0, float v1) {
    int cb = jj >> 6, wcol = jj & 63;
    int up = (wcol >> 3) ^ (m & 7);
    long off = (long)cb * 8192 + m * 64 + up * 8 + (wcol & 7);
    fp16 h0 = __float2half(v0);
    fp16 h1 = __float2half(v1);
    *(__half2*)(hi + off) = __half2(h0, h1);
    *(__half2*)(lo + off) = __half2(
        __float2half(v0 - __half2float(h0)),
        __float2half(v1 - __half2float(h1)));
}

// -------------------- persistent encoder (bidirectional GRU) ---------------
__global__ void __launch_bounds__(256, 1)
encoder_kernel(const float* __restrict__ bh_f, const float* __restrict__ bh_b) {
    extern __shared__ __align__(16) char smem[];
    uint32_t sm = (uint32_t)__cvta_generic_to_shared(smem);
    uint32_t mb = sm + 3 * STG_E;
    const int tid = threadIdx.x, lane = tid & 31;
    const int m0 = (tid >> 5) * 16;
    const int dir = blockIdx.x >> 6;
    const int jt = blockIdx.x & 63;
    const int j0 = jt * 16;

    if (tid == 0) { mbar_init(mb, 1); mbar_init(mb + 8, 1); mbar_init(mb + 16, 1); }
    __syncthreads();
    int stph[3] = {0, 0, 0};

    const char* Wh = (const char*)(dir ? g_whhb_hi : g_whhf_hi) + (long)jt * WTILE_E;
    const char* Wl = (const char*)(dir ? g_whhb_lo : g_whhf_lo) + (long)jt * WTILE_E;
    const float* gi = dir ? g_gib : g_gif;
    const float* bh = dir ? bh_b : bh_f;

    float bh2[2][6];
#pragma unroll
    for (int ct = 0; ct < 2; ct++) {
        int jj = j0 + ct * 8 + (lane & 3) * 2;
#pragma unroll
        for (int g = 0; g < 3; g++) {
            bh2[ct][g * 2]     = bh[g * H_ + jj];
            bh2[ct][g * 2 + 1] = bh[g * H_ + jj + 1];
        }
    }

#pragma unroll 1
    for (int t = 0; t < T_; t++) {
        const int cur = t & 1, nxt = cur ^ 1;
        const char* Ah = (const char*)(dir ? g_hbc_hi[cur] : g_hfc_hi[cur]);
        const char* Al = (const char*)(dir ? g_hbc_lo[cur] : g_hfc_lo[cur]);
        const float* hc = dir ? g_hb[cur] : g_hf[cur];
        float*       hn = dir ? g_hb[nxt] : g_hf[nxt];
        bf16* chi = dir ? g_hbc_hi[nxt] : g_hfc_hi[nxt];
        bf16* clo = dir ? g_hbc_lo[nxt] : g_hfc_lo[nxt];
        const int tstep = dir ? (T_ - 1 - t) : t;

        float acc[3][2][4] = {};
        mma_pass_enc(Ah, Al, Wh, Wl, sm, mb, stph, acc);

#pragma unroll
        for (int ct = 0; ct < 2; ct++) {
            int jj = j0 + ct * 8 + (lane & 3) * 2;
#pragma unroll
            for (int half = 0; half < 2; half++) {
                int m = m0 + (lane >> 2) + half * 8;
                long gb = ((long)m * T_ + tstep) * H3_ + jj;
                float2 gr = *(const float2*)(gi + gb);
                float2 gz = *(const float2*)(gi + gb + H_);
                float2 gn = *(const float2*)(gi + gb + 2 * H_);
                float2 hp = *(const float2*)(hc + (long)m * H_ + jj);
                float r0 = sigmoidf_(gr.x + acc[0][ct][half * 2]     + bh2[ct][0]);
                float r1 = sigmoidf_(gr.y + acc[0][ct][half * 2 + 1] + bh2[ct][1]);
                float u0 = sigmoidf_(gz.x + acc[1][ct][half * 2]     + bh2[ct][2]);
                float u1 = sigmoidf_(gz.y + acc[1][ct][half * 2 + 1] + bh2[ct][3]);
                float n0 = tanhf(gn.x + r0 * (acc[2][ct][half * 2]     + bh2[ct][4]));
                float n1 = tanhf(gn.y + r1 * (acc[2][ct][half * 2 + 1] + bh2[ct][5]));
                float v0 = (1.f - u0) * n0 + u0 * hp.x;
                float v1 = (1.f - u1) * n1 + u1 * hp.y;
                *(float2*)(hn + (long)m * H_ + jj) = make_float2(v0, v1);
                store_chunked(chi, clo, m, jj, v0, v1);
            }
        }
        grid_barrier();
    }
}

// ---------- persistent decoder: software-pipelined, 1 barrier/window -------
// 256 CTAs, 2/SM. Window k (k=0..T):
//   role0 (bid<128): phaseA(k) for k<T      [h0(k) -> h0(k+1)]
//   role1 (bid>=128): step s=k-1 tail for k>=1: accH(s) + accI(s) + epiB(s)
__global__ void __launch_bounds__(256, 2)
decoder_kernel(const float* __restrict__ b_hh_g,
               const float* __restrict__ b_ih_g2, const float* __restrict__ b_hh_g2) {
    extern __shared__ __align__(16) char smem[];
    uint32_t sm = (uint32_t)__cvta_generic_to_shared(smem);
    uint32_t mb = sm + 2 * STG_D;
    const int tid = threadIdx.x, lane = tid & 31;
    const int m0 = (tid >> 5) * 16;
    const bool role0 = blockIdx.x < 128;
    const int jt = blockIdx.x & 127;
    const int j0 = jt * 8;
    const int jj = j0 + (lane & 3) * 2;

    if (tid == 0) { mbar_init(mb, 1); mbar_init(mb + 8, 1); }
    __syncthreads();
    int stph[2] = {0, 0};

    const char* Wg = (const char*)g_whhg_f  + (long)jt * WTILE_D;
    const char* Wi = (const char*)g_wihg2_f + (long)jt * WTILE_D;
    const char* Wh = (const char*)g_whhg2_f + (long)jt * WTILE_D;

    float bg6[6], bi6[6], bh6[6];
#pragma unroll
    for (int g = 0; g < 3; g++) {
        bg6[g * 2] = b_hh_g[g * H_ + jj];   bg6[g * 2 + 1] = b_hh_g[g * H_ + jj + 1];
        bi6[g * 2] = b_ih_g2[g * H_ + jj];  bi6[g * 2 + 1] = b_ih_g2[g * H_ + jj + 1];
        bh6[g * 2] = b_hh_g2[g * H_ + jj];  bh6[g * 2 + 1] = b_hh_g2[g * H_ + jj + 1];
    }

#pragma unroll 1
    for (int k = 0; k <= T_; k++) {
        if (role0) {
            if (k < T_) {
                const int cur = k & 1, nxt = cur ^ 1;
                float acc[3][4] = {};
                mma_pass_dec((const char*)g_h0c_hi[cur], (const char*)g_h0c_lo[cur],
                             Wg, sm, mb, stph, acc);
#pragma unroll
                for (int half = 0; half < 2; half++) {
                    int m = m0 + (lane >> 2) + half * 8;
                    long gb = ((long)m * T_ + k) * H3_ + jj;
                    long zb = (long)m * H3_ + jj;
                    float2 gr = *(const float2*)(g_gid + gb);
                    float2 gz = *(const float2*)(g_gid + gb + H_);
                    float2 gn = *(const float2*)(g_gid + gb + 2 * H_);
                    float2 zr = *(const float2*)(g_zi + zb);
                    float2 zz = *(const float2*)(g_zi + zb + H_);
                    float2 zn = *(const float2*)(g_zi + zb + 2 * H_);
                    float2 hp = *(const float2*)(g_h0[cur] + (long)m * H_ + jj);
                    float r0 = sigmoidf_(gr.x + zr.x + acc[0][half * 2]     + bg6[0]);
                    float r1 = sigmoidf_(gr.y + zr.y + acc[0][half * 2 + 1] + bg6[1]);
                    float u0 = sigmoidf_(gz.x + zz.x + acc[1][half * 2]     + bg6[2]);
                    float u1 = sigmoidf_(gz.y + zz.y + acc[1][half * 2 + 1] + bg6[3]);
                    float n0 = tanhf(gn.x + zn.x + r0 * (acc[2][half * 2]     + bg6[4]));
                    float n1 = tanhf(gn.y + zn.y + r1 * (acc[2][half * 2 + 1] + bg6[5]));
                    float v0 = (1.f - u0) * n0 + u0 * hp.x;
                    float v1 = (1.f - u1) * n1 + u1 * hp.y;
                    *(float2*)(g_h0[nxt] + (long)m * H_ + jj) = make_float2(v0, v1);
                    store_chunked_f16(g_h0c_hi[nxt], g_h0c_lo[nxt], m, jj, v0, v1);
                }
            }
        } else if (k >= 1) {
            const int s = k - 1;
            const int scur = s & 1, snxt = scur ^ 1;
            const char* h1p_hi = (s == 0) ? (const char*)g_h0c_hi[1] : (const char*)g_h1c_hi[scur];
            const char* h1p_lo = (s == 0) ? (const char*)g_h0c_lo[1] : (const char*)g_h1c_lo[scur];
            const float* h1p_f = (s == 0) ? g_h0[1] : g_h1[scur];

            float accH[3][4] = {};
            float accI[3][4] = {};
            mma_pass_dec(h1p_hi, h1p_lo, Wh, sm, mb, stph, accH);
            mma_pass_dec((const char*)g_h0c_hi[snxt], (const char*)g_h0c_lo[snxt],
                         Wi, sm, mb, stph, accI);
#pragma unroll
            for (int half = 0; half < 2; half++) {
                int m = m0 + (lane >> 2) + half * 8;
                float2 hp = *(const float2*)(h1p_f + (long)m * H_ + jj);
                float r0 = sigmoidf_((accI[0][half * 2]     + bi6[0]) + (accH[0][half * 2]     + bh6[0]));
                float r1 = sigmoidf_((accI[0][half * 2 + 1] + bi6[1]) + (accH[0][half * 2 + 1] + bh6[1]));
                float u0 = sigmoidf_((accI[1][half * 2]     + bi6[2]) + (accH[1][half * 2]     + bh6[2]));
                float u1 = sigmoidf_((accI[1][half * 2 + 1] + bi6[3]) + (accH[1][half * 2 + 1] + bh6[3]));
                float n0 = tanhf((accI[2][half * 2]     + bi6[4]) + r0 * (accH[2][half * 2]     + bh6[4]));
                float n1 = tanhf((accI[2][half * 2 + 1] + bi6[5]) + r1 * (accH[2][half * 2 + 1] + bh6[5]));
                float v0 = (1.f - u0) * n0 + u0 * hp.x;
                float v1 = (1.f - u1) * n1 + u1 * hp.y;
                *(float2*)(g_h1[snxt] + (long)m * H_ + jj) = make_float2(v0, v1);
                store_chunked_f16(g_h1c_hi[snxt], g_h1c_lo[snxt], m, jj, v0, v1);
                bf16 h0b = __float2bfloat16(v0);
                bf16 h1b = __float2bfloat16(v1);
                long ho = ((long)m * T_ + s) * H_ + jj;
                *(__nv_bfloat162*)(g_h1a_hi + ho) = __nv_bfloat162(h0b, h1b);
                *(__nv_bfloat162*)(g_h1a_lo + ho) = __nv_bfloat162(
                    __float2bfloat16(v0 - __bfloat162float(h0b)),
                    __float2bfloat16(v1 - __bfloat162float(h1b)));
            }
        }
        grid_barrier();
    }
}

// ------------------- split-bf16 batched GEMM (mma.sync) ---------------------
struct BfArgs {
    const bf16 *Ah, *Al, *Wh, *Wl;
    const float* bias;
    float* C;
    long lda, ldb, ldc;
    int  N, kchunks;
};

__global__ void __launch_bounds__(256, 2) gemm_bf16_kernel(BfArgs a) {
    extern __shared__ char smem[];
    uint32_t sm = (uint32_t)__cvta_generic_to_shared(smem);
    const long bm = (long)blockIdx.y * 128;
    const int  bn = blockIdx.x * 64;
    const int tid = threadIdx.x, lane = tid & 31;
    const int m0 = (tid >> 5) * 16;
    const int arow  = m0 + (lane & 15);
    const int ahalf = (lane >> 4) * 16;
    const int brow  = lane & 7;
    const int bhalf = ((lane >> 3) & 1) * 16;

    float acc[8][4];
#pragma unroll
    for (int nt = 0; nt < 8; nt++)
#pragma unroll
        for (int q = 0; q < 4; q++) acc[nt][q] = 0.f;

    auto issue = [&](int c, int st) {
        uint32_t base = sm + st * STAGE_G;
        long k0 = (long)c * KCH;
#pragma unroll
        for (int i = 0; i < 8; i++) {
            int u = tid + i * 256;
            int mat = u >= 1024; int r = mat ? u - 1024 : u;
            int row = r >> 3, seg = r & 7;
            cpa16(base + (mat ? ABYTES : 0) + row * ROWB + seg * 16,
                  (mat ? a.Al : a.Ah) + (bm + row) * a.lda + k0 + seg * 8);
        }
#pragma unroll
        for (int i = 0; i < 4; i++) {
            int u = tid + i * 256;
            int mat = u >= 512; int r = mat ? u - 512 : u;
            int row = r >> 3, seg = r & 7;
            cpa16(base + 2 * ABYTES + (mat ? BBYT_G : 0) + row * ROWB + seg * 16,
                  (mat ? a.Wl : a.Wh) + (long)(bn + row) * a.ldb + k0 + seg * 8);
        }
    };

    issue(0, 0); cp_commit();
#pragma unroll 1
    for (int c = 0; c < a.kchunks; c++) {
        if (c < a.kchunks - 1) { issue(c + 1, (c + 1) & 1); cp_commit(); cp_wait<1>(); }
        else                   { cp_wait<0>(); }
        __syncthreads();
        uint32_t base = sm + (c & 1) * STAGE_G;
#pragma unroll
        for (int s = 0; s < 4; s++) {
            uint32_t aoff = base + arow * ROWB + ahalf + s * 32;
            uint32_t a_hi[4], a_lo[4];
            ldsm4(a_hi, aoff);
            ldsm4(a_lo, aoff + ABYTES);
#pragma unroll
            for (int nt = 0; nt < 8; nt++) {
                uint32_t boff = base + 2 * ABYTES + (nt * 8 + brow) * ROWB + bhalf + s * 32;
                uint32_t b_hi[2], b_lo[2];
                ldsm2(b_hi, boff);
                ldsm2(b_lo, boff + BBYT_G);
                mma16816(acc[nt], a_hi, b_hi);
                mma16816(acc[nt], a_hi, b_lo);
                mma16816(acc[nt], a_lo, b_hi);
            }
        }
        __syncthreads();
    }

#pragma unroll
    for (int nt = 0; nt < 8; nt++) {
        int gn = bn + nt * 8 + (lane & 3) * 2;
        float b0 = 0.f, b1 = 0.f;
        if (a.bias) {
            if (gn < a.N)     b0 = a.bias[gn];
            if (gn + 1 < a.N) b1 = a.bias[gn + 1];
        }
#pragma unroll
        for (int half = 0; half < 2; half++) {
            long m = bm + m0 + (lane >> 2) + half * 8;
            if (gn < a.N)     a.C[m * a.ldc + gn]     = acc[nt][half * 2]     + b0;
            if (gn + 1 < a.N) a.C[m * a.ldc + gn + 1] = acc[nt][half * 2 + 1] + b1;
        }
    }
}

// ------------------------------- fp32 GEMM ----------------------------------
struct GArgs {
    const float* A;  long lda;
    const float* W;  long ldw;
    const float* bias;
    float*       C;  long ldc;
    int M, N, K;
};
constexpr int GBM = 128, GBN = 128, GBK = 16;

__global__ void __launch_bounds__(256, 2) gemm_nt_kernel(GArgs g0, GArgs g1) {
    GArgs g = (blockIdx.z == 0) ? g0 : g1;
    const int bm = blockIdx.y * GBM;
    const int bn = blockIdx.x * GBN;
    if (bm >= g.M || bn >= g.N) return;
    __shared__ float As[GBK][GBM + 4];
    __shared__ ull   Bs[GBK][GBN + 1];
    const int tid = threadIdx.x;
    const int tx  = tid & 15, ty = tid >> 4;
    const int r0  = ty * 8;

    ull acc[4][8];
#pragma unroll
    for (int p = 0; p < 4; p++)
#pragma unroll
        for (int c = 0; c < 8; c++) acc[p][c] = 0ull;

    for (int k0 = 0; k0 < g.K; k0 += GBK) {
#pragma unroll
        for (int i = 0; i < 8; i++) {
            int idx = tid + i * 256;
            int m = idx >> 4, kk = idx & 15;
            int gm = bm + m, gk = k0 + kk;
            float v = 0.f;
            if (gm < g.M && gk < g.K) v = g.A[(long)gm * g.lda + gk];
            As[kk][m] = v;
        }
#pragma unroll
        for (int i = 0; i < 8; i++) {
            int idx = tid + i * 256;
            int n = idx >> 4, kk = idx & 15;
            int gn = bn + n, gk = k0 + kk;
            float v = 0.f;
            if (gn < g.N && gk < g.K) v = g.W[(long)gn * g.ldw + gk];
            Bs[kk][(n & 7) * 16 + (n >> 3)] = pack2(v, v);
        }
        __syncthreads();
#pragma unroll
        for (int kk = 0; kk < GBK; kk++) {
            ull a[4], b[8];
#pragma unroll
            for (int p = 0; p < 4; p++) a[p] = *(const ull*)&As[kk][r0 + 2 * p];
#pragma unroll
            for (int c = 0; c < 8; c++) b[c] = Bs[kk][c * 16 + tx];
#pragma unroll
            for (int p = 0; p < 4; p++)
#pragma unroll
                for (int c = 0; c < 8; c++) fma2(acc[p][c], a[p], b[c]);
        }
        __syncthreads();
    }
#pragma unroll
    for (int p = 0; p < 4; p++) {
        int gm = bm + r0 + 2 * p;
#pragma unroll
        for (int c = 0; c < 8; c++) {
            int gn = bn + tx * 8 + c;
            if (gn >= g.N) continue;
            float2 v = unpack2(acc[p][c]);
            float bias = g.bias ? g.bias[gn] : 0.f;
            if (gm < g.M)     g.C[(long)gm * g.ldc + gn]       = v.x + bias;
            if (gm + 1 < g.M) g.C[(long)(gm + 1) * g.ldc + gn] = v.y + bias;
        }
    }
}

// --------------------------- elementwise kernels ----------------------------
__global__ void init_kernel(const float* __restrict__ x) {
    long stride = (long)gridDim.x * blockDim.x;
    long i0 = (long)blockIdx.x * blockDim.x + threadIdx.x;
    if (i0 == 0) { g_bar_count = 0; g_bar_gen = 0; }
    for (long i = i0; i < BH_; i += stride) {
        g_hf[0][i] = 0.f; g_hb[0][i] = 0.f;
        g_hfc_hi[0][i] = bf16(0.f); g_hfc_lo[0][i] = bf16(0.f);
        g_hbc_hi[0][i] = bf16(0.f); g_hbc_lo[0][i] = bf16(0.f);
    }
    for (long i = i0; i < BT_ * R_; i += stride) {
        int  r = (int)(i % R_);
        long m = i / R_;
        int  t = (int)(m % T_);
        g_decin[i] = (t == 0) ? ((r == R_ - 1) ? 1.f : 0.f) : x[i - R_];
    }
}

// W [3H x H] -> [64 jt][16 c][48 rows x 128B] chunk-swizzled (encoder, bf16 hi/lo)
__global__ void convert_w_tiled_enc(const float* __restrict__ src,
                                    bf16* __restrict__ hi, bf16* __restrict__ lo) {
    long stride = (long)gridDim.x * blockDim.x;
    for (long q = (long)blockIdx.x * blockDim.x + threadIdx.x; q < 393216; q += stride) {
        int up = (int)(q & 7);
        long r = q >> 3;
        int rw = (int)(r % 48);
        long rc = r / 48;
        int c = (int)(rc & 15);
        int jt = (int)(rc >> 4);
        int u = up ^ (rw & 7);
        int g = rw >> 4;
        int j = jt * 16 + (rw & 15);
        int k = c * 64 + u * 8;
        const float* s = src + (long)(g * H_ + j) * H_ + k;
        bf16 h8[8], l8[8];
#pragma unroll
        for (int e = 0; e < 8; e++) {
            float w = s[e];
            bf16 h = __float2bfloat16(w);
            h8[e] = h;
            l8[e] = __float2bfloat16(w - __bfloat162float(h));
        }
        *(uint4*)(hi + q * 8) = *(uint4*)h8;
        *(uint4*)(lo + q * 8) = *(uint4*)l8;
    }
}

// W [3H x H] -> [128 jt][16 c][24 rows x 128B] chunk-swizzled (decoder, fp16 single)
__global__ void convert_w_tiled_dec(const float* __restrict__ src,
                                    fp16* __restrict__ wd) {
    long stride = (long)gridDim.x * blockDim.x;
    for (long q = (long)blockIdx.x * blockDim.x + threadIdx.x; q < 393216; q += stride) {
        int up = (int)(q & 7);
        long r = q >> 3;
        int rw = (int)(r % 24);
        long rc = r / 24;
        int c = (int)(rc & 15);
        int jt = (int)(rc >> 4);
        int u = up ^ (rw & 7);
        int g = rw >> 3;
        int j = jt * 8 + (rw & 7);
        int k = c * 64 + u * 8;
        const float* s = src + (long)(g * H_ + j) * H_ + k;
        fp16 h8[8];
#pragma unroll
        for (int e = 0; e < 8; e++) h8[e] = __float2half(s[e]);
        *(uint4*)(wd + q * 8) = *(uint4*)h8;
    }
}

// h [128 x 1024] row-major fp32 -> chunk-swizzled fp16 hi/lo (decoder init)
__global__ void convert_h_chunked(const float* __restrict__ src,
                                  fp16* __restrict__ hi, fp16* __restrict__ lo) {
    long stride = (long)gridDim.x * blockDim.x;
    for (long q = (long)blockIdx.x * blockDim.x + threadIdx.x; q < 16384; q += stride) {
        int up = (int)(q & 7);
        int row = (int)((q >> 3) & 127);
        int c = (int)(q >> 10);
        int u = up ^ (row & 7);
        int k = c * 64 + u * 8;
        const float* s = src + (long)row * H_ + k;
        fp16 h8[8], l8[8];
#pragma unroll
        for (int e = 0; e < 8; e++) {
            float w = s[e];
            fp16 h = __float2half(w);
            h8[e] = h;
            l8[e] = __float2half(w - __half2float(h));
        }
        *(uint4*)(hi + q * 8) = *(uint4*)h8;
        *(uint4*)(lo + q * 8) = *(uint4*)l8;
    }
}

__global__ void convert_pad_kernel(const float* __restrict__ src, long srcld,
                                   long srcrows, int cols, long dstld, long rows,
                                   bf16* __restrict__ hi, bf16* __restrict__ lo) {
    long stride = (long)gridDim.x * blockDim.x;
    long total = rows * dstld;
    for (long i = (long)blockIdx.x * blockDim.x + threadIdx.x; i < total; i += stride) {
        long r = i / dstld;
        long c = i - r * dstld;
        float v = (r < srcrows && c < cols) ? src[r * srcld + c] : 0.f;
        bf16 h = __float2bfloat16(v);
        hi[i] = h;
        lo[i] = __float2bfloat16(v - __bfloat162float(h));
    }
}

__global__ void henc_kernel() {
    int i = blockIdx.x * blockDim.x + threadIdx.x;
    if (i >= B_ * H_) return;
    int b = i / H_, jj = i % H_;
    g_henc[(long)b * 2 * H_ + jj]      = g_hf[0][i];
    g_henc[(long)b * 2 * H_ + H_ + jj] = g_hb[0][i];
}

__global__ void zstd_kernel(const float* __restrict__ eps,
                            const float* __restrict__ chroma,
                            const float* __restrict__ mu_out,
                            float* __restrict__ std_out,
                            float* __restrict__ z_out) {
    int b = blockIdx.x;
    int jj = threadIdx.x;
    if (jj < Z2_) {
        float mu = mu_out[(long)b * Z2_ + jj];
        float sd = expf(g_var[(long)b * Z2_ + jj]);
        float z  = mu + sd * eps[(long)b * Z2_ + jj];
        std_out[(long)b * Z2_ + jj] = sd;
        z_out[(long)b * ZC_ + jj]   = z;
        g_zbuf[(long)b * ZC_ + jj]  = z;
    } else if (jj < ZC_) {
        float cv = chroma[(long)b * C_ + (jj - Z2_)];
        z_out[(long)b * ZC_ + jj]  = cv;
        g_zbuf[(long)b * ZC_ + jj] = cv;
    }
}

__global__ void logsoftmax_kernel(const float* __restrict__ logits,
                                  float* __restrict__ out) {
    long warp = ((long)blockIdx.x * blockDim.x + threadIdx.x) >> 5;
    int  lane = threadIdx.x & 31;
    if (warp >= BT_) return;
    const float* row = logits + warp * R_;
    float mx = -1e30f;
    for (int jj = lane; jj < R_; jj += 32) mx = fmaxf(mx, row[jj]);
#pragma unroll
    for (int o = 16; o; o >>= 1) mx = fmaxf(mx, __shfl_xor_sync(0xffffffff, mx, o));
    float s = 0.f;
    for (int jj = lane; jj < R_; jj += 32) s += expf(row[jj] - mx);
#pragma unroll
    for (int o = 16; o; o >>= 1) s += __shfl_xor_sync(0xffffffff, s, o);
    float lse = mx + logf(s);
    float* orow = out + warp * R_;
    for (int jj = lane; jj < R_; jj += 32) orow[jj] = row[jj] - lse;
}

// ------------------------------ host helpers --------------------------------
static void launch_gemm2(const GArgs& a, const GArgs& b) {
    int M = a.M > b.M ? a.M : b.M;
    int N = a.N > b.N ? a.N : b.N;
    dim3 grid((N + GBN - 1) / GBN, (M + GBM - 1) / GBM, 2);
    gemm_nt_kernel<<<grid, 256>>>(a, b);
}
static void launch_bf_gemm(const BfArgs& a) {
    dim3 grid((a.N + 63) / 64, 32768 / 128, 1);
    gemm_bf16_kernel<<<grid, 256, SMEM_G>>>(a);
}
template <typename Tp>
static float* sym_addr(Tp& sym) {
    void* p = nullptr;
    cudaGetSymbolAddress(&p, sym);
    return (float*)p;
}
template <typename Tp>
static bf16* sym_addr_bf(Tp& sym) {
    void* p = nullptr;
    cudaGetSymbolAddress(&p, sym);
    return (bf16*)p;
}
template <typename Tp>
static fp16* sym_addr_f16(Tp& sym) {
    void* p = nullptr;
    cudaGetSymbolAddress(&p, sym);
    return (fp16*)p;
}
} // namespace

extern "C" void kernel_launch(void* const* d_in, const int* in_sizes, int n_in,
                              void* d_out, int out_size) {
    (void)in_sizes; (void)n_in; (void)out_size;
    const float* x        = (const float*)d_in[0];
    const float* chroma   = (const float*)d_in[1];
    const float* eps      = (const float*)d_in[2];
    const float* w_ih_f   = (const float*)d_in[3];
    const float* w_hh_f   = (const float*)d_in[4];
    const float* b_ih_f   = (const float*)d_in[5];
    const float* b_hh_f   = (const float*)d_in[6];
    const float* w_ih_b   = (const float*)d_in[7];
    const float* w_hh_b   = (const float*)d_in[8];
    const float* b_ih_b   = (const float*)d_in[9];
    const float* b_hh_b   = (const float*)d_in[10];
    const float* w_mu     = (const float*)d_in[11];
    const float* b_mu     = (const float*)d_in[12];
    const float* w_var    = (const float*)d_in[13];
    const float* b_var    = (const float*)d_in[14];
    const float* w_init   = (const float*)d_in[15];
    const float* b_init   = (const float*)d_in[16];
    const float* w_ih_g   = (const float*)d_in[17];
    const float* w_hh_g   = (const float*)d_in[18];
    const float* b_ih_g   = (const float*)d_in[19];
    const float* b_hh_g   = (const float*)d_in[20];
    const float* w_ih_g2  = (const float*)d_in[21];
    const float* w_hh_g2  = (const float*)d_in[22];
    const float* b_ih_g2  = (const float*)d_in[23];
    const float* b_hh_g2  = (const float*)d_in[24];
    const float* w_out    = (const float*)d_in[25];
    const float* b_out    = (const float*)d_in[26];

    float* out = (float*)d_out;
    const long MU_OFF  = BT_ * R_;
    const long STD_OFF = MU_OFF + (long)B_ * Z2_;
    const long Z_OFF   = STD_OFF + (long)B_ * Z2_;

    float* p_gif   = sym_addr(g_gif);
    float* p_gib   = sym_addr(g_gib);
    float* p_gid   = sym_addr(g_gid);
    float* p_zi    = sym_addr(g_zi);
    float* p_h0    = sym_addr(g_h0);
    float* p_henc  = sym_addr(g_henc);
    float* p_var   = sym_addr(g_var);
    float* p_zbuf  = sym_addr(g_zbuf);
    float* p_decin = sym_addr(g_decin);
    float* p_logit = sym_addr(g_logits);

    cudaFuncSetAttribute(encoder_kernel,   cudaFuncAttributeMaxDynamicSharedMemorySize, SMEM_E);
    cudaFuncSetAttribute(decoder_kernel,   cudaFuncAttributeMaxDynamicSharedMemorySize, SMEM_D2);
    cudaFuncSetAttribute(gemm_bf16_kernel, cudaFuncAttributeMaxDynamicSharedMemorySize, SMEM_G);

    // 1. prologue
    init_kernel<<<512, 256>>>(x);

    // 1b. recurrent weights: encoder bf16 hi/lo, decoder fp16 single
    convert_w_tiled_enc<<<512, 256>>>(w_hh_f,  sym_addr_bf(g_whhf_hi),  sym_addr_bf(g_whhf_lo));
    convert_w_tiled_enc<<<512, 256>>>(w_hh_b,  sym_addr_bf(g_whhb_hi),  sym_addr_bf(g_whhb_lo));
    convert_w_tiled_dec<<<512, 256>>>(w_hh_g,  sym_addr_f16(g_whhg_f));
    convert_w_tiled_dec<<<512, 256>>>(w_ih_g2, sym_addr_f16(g_wihg2_f));
    convert_w_tiled_dec<<<512, 256>>>(w_hh_g2, sym_addr_f16(g_whhg2_f));

    // 1c. batched-GEMM operands -> split-bf16 with K padding
    convert_pad_kernel<<<1024, 256>>>(x,       R_,  BT_,  R_,  KPAD, BT_,
                                      sym_addr_bf(g_xc_hi), sym_addr_bf(g_xc_lo));
    convert_pad_kernel<<<1024, 256>>>(p_decin, R_,  BT_,  R_,  KPAD, BT_,
                                      sym_addr_bf(g_dc_hi), sym_addr_bf(g_dc_lo));
    convert_pad_kernel<<<512, 256>>>(w_ih_f,  R_,  H3_,  R_,  KPAD, H3_,
                                     sym_addr_bf(g_wihf_hi), sym_addr_bf(g_wihf_lo));
    convert_pad_kernel<<<512, 256>>>(w_ih_b,  R_,  H3_,  R_,  KPAD, H3_,
                                     sym_addr_bf(g_wihb_hi), sym_addr_bf(g_wihb_lo));
    convert_pad_kernel<<<512, 256>>>(w_ih_g,  410, H3_,  R_,  KPAD, H3_,
                                     sym_addr_bf(g_wihg_hi), sym_addr_bf(g_wihg_lo));
    convert_pad_kernel<<<256, 256>>>(w_out,   H_,  R_,   H_,  H_,   192,
                                     sym_addr_bf(g_wout_hi), sym_addr_bf(g_wout_lo));

    // 2/3. input-gate GEMMs (tensor cores)
    launch_bf_gemm({sym_addr_bf(g_xc_hi), sym_addr_bf(g_xc_lo),
                    sym_addr_bf(g_wihf_hi), sym_addr_bf(g_wihf_lo),
                    b_ih_f, p_gif, KPAD, KPAD, H3_, H3_, KPAD / KCH});
    launch_bf_gemm({sym_addr_bf(g_xc_hi), sym_addr_bf(g_xc_lo),
                    sym_addr_bf(g_wihb_hi), sym_addr_bf(g_wihb_lo),
                    b_ih_b, p_gib, KPAD, KPAD, H3_, H3_, KPAD / KCH});
    launch_bf_gemm({sym_addr_bf(g_dc_hi), sym_addr_bf(g_dc_lo),
                    sym_addr_bf(g_wihg_hi), sym_addr_bf(g_wihg_lo),
                    nullptr, p_gid, KPAD, KPAD, H3_, H3_, KPAD / KCH});

    // 4. persistent bidirectional encoder (bf16 3-term, unchanged)
    encoder_kernel<<<128, 256, SMEM_E>>>(b_hh_f, b_hh_b);

    // 5. concat final hiddens
    henc_kernel<<<(B_ * H_ + 255) / 256, 256>>>();

    // 6. VAE head
    GArgs gmu {p_henc, 2 * H_, w_mu,  2 * H_, b_mu,  out + MU_OFF, Z2_, B_, Z2_, 2 * H_};
    GArgs gvar{p_henc, 2 * H_, w_var, 2 * H_, b_var, p_var,        Z2_, B_, Z2_, 2 * H_};
    launch_gemm2(gmu, gvar);

    // 7. reparameterize + concat chroma
    zstd_kernel<<<B_, 288>>>(eps, chroma, out + MU_OFF, out + STD_OFF, out + Z_OFF);

    // 8. hx0 + z-part of decoder L1 input gates
    GArgs ghx0{p_zbuf, ZC_, w_init, ZC_, b_init, p_h0, H_, B_, H_, ZC_};
    GArgs gzi {p_zbuf, ZC_, w_ih_g + 130, 410, b_ih_g, p_zi, H3_, B_, H3_, ZC_};
    launch_gemm2(ghx0, gzi);

    // 8b. hx0 -> chunk-swizzled split-fp16
    convert_h_chunked<<<64, 256>>>(p_h0, sym_addr_f16(g_h0c_hi), sym_addr_f16(g_h0c_lo));

    // 9. persistent decoder (software-pipelined, fp16 2-term)
    decoder_kernel<<<256, 256, SMEM_D2>>>(b_hh_g, b_ih_g2, b_hh_g2);

    // 10. batched output projection
    launch_bf_gemm({sym_addr_bf(g_h1a_hi), sym_addr_bf(g_h1a_lo),
                    sym_addr_bf(g_wout_hi), sym_addr_bf(g_wout_lo),
                    b_out, p_logit, H_, H_, R_, R_, H_ / KCH});

    // 11. log_softmax
    logsoftmax_kernel<<<(int)((BT_ * 32 + 255) / 256), 256>>>(p_logit, out);
}